// round 13
// baseline (speedup 1.0000x reference)
#include <cuda_runtime.h>
#include <cuda_bf16.h>
#include <math.h>
#include <stdint.h>

#define B 4
#define S 2048
#define D 512
#define H 8
#define DK 64
#define U 53
#define BH (B*H)

// ---------------- scratch ----------------
__device__ float g_Q[B*H*S*DK];       // fp32 [bh][s][k]
__device__ float g_K[B*H*S*DK];
__device__ float g_spars[B*H*S];
__device__ int   g_topidx[B*H*U];
__device__ float g_xpart[32*B*D];
__device__ float g_xsum[B*D];
__device__ float g_meanV[B*D];
__device__ float g_ybase[B*D];
__device__ float g_outcat[B*U*D];
__device__ float g_sumK[BH*DK];
__device__ int   g_sidx[BH*S];
__device__ float g_candv[BH*8*U];
__device__ int   g_candi[BH*8*U];
// bf16 hi operands (written by proj epilogue)
__device__ __nv_bfloat16 g_Qhi[BH*S*DK];
__device__ __nv_bfloat16 g_Khi[BH*S*DK];
// split bf16 inputs for proj mma
__device__ __nv_bfloat16 g_xhi[B*S*D];
__device__ __nv_bfloat16 g_xlo[B*S*D];
__device__ __nv_bfloat16 g_wqhi[D*D];
__device__ __nv_bfloat16 g_wqlo[D*D];
__device__ __nv_bfloat16 g_wkhi[D*D];
__device__ __nv_bfloat16 g_wklo[D*D];

// ================= warp-mma helpers =================
__device__ __forceinline__ uint32_t smem_u32(const void* p) {
    uint32_t a;
    asm("{ .reg .u64 t; cvta.to.shared.u64 t, %1; cvt.u32.u64 %0, t; }" : "=r"(a) : "l"(p));
    return a;
}
__device__ __forceinline__ void ldsm_x4(uint32_t& r0, uint32_t& r1, uint32_t& r2, uint32_t& r3, uint32_t addr) {
    asm volatile("ldmatrix.sync.aligned.m8n8.x4.shared.b16 {%0,%1,%2,%3}, [%4];"
        : "=r"(r0), "=r"(r1), "=r"(r2), "=r"(r3) : "r"(addr));
}
__device__ __forceinline__ void mma_bf16(float& c0, float& c1, float& c2, float& c3,
                                         uint32_t a0, uint32_t a1, uint32_t a2, uint32_t a3,
                                         uint32_t b0, uint32_t b1) {
    asm volatile("mma.sync.aligned.m16n8k16.row.col.f32.bf16.bf16.f32 "
        "{%0,%1,%2,%3}, {%4,%5,%6,%7}, {%8,%9}, {%0,%1,%2,%3};"
        : "+f"(c0), "+f"(c1), "+f"(c2), "+f"(c3)
        : "r"(a0), "r"(a1), "r"(a2), "r"(a3), "r"(b0), "r"(b1));
}
#define CP_ASYNC16(dst, src) \
    asm volatile("cp.async.cg.shared.global [%0], [%1], 16;" :: "r"(dst), "l"(src))
#define CP_COMMIT() asm volatile("cp.async.commit_group;" ::: "memory")
#define CP_WAIT1()  asm volatile("cp.async.wait_group 1;" ::: "memory")

// ---------------- column sums of x (partials) ----------------
__global__ void sumx_part_kernel(const float* __restrict__ x) {
    int blk = blockIdx.x;
    int b = blk >> 5, sc = blk & 31;
    int d = threadIdx.x;
    const float* p = x + ((size_t)b*S + sc*64)*D + d;
    float acc = 0.f;
    #pragma unroll 8
    for (int s = 0; s < 64; s++) acc += p[(size_t)s*D];
    g_xpart[(size_t)blk*D + d] = acc;
}

// ---------------- fp32 -> split-bf16 for x, wq, wk ----------------
#define XU (B*S*D/8)
#define WU (D*D/8)
__global__ void convert_xw_kernel(const float* __restrict__ x, const float* __restrict__ wq,
                                  const float* __restrict__ wk) {
    int id = blockIdx.x * blockDim.x + threadIdx.x;
    if (id >= XU + 2*WU) return;
    const float* src;
    __nv_bfloat16 *dh, *dl;
    int u;
    if (id < XU)                { u = id;            src = x  + (size_t)u*8; dh = g_xhi;  dl = g_xlo;  }
    else if (id < XU + WU)      { u = id - XU;       src = wq + (size_t)u*8; dh = g_wqhi; dl = g_wqlo; }
    else                        { u = id - XU - WU;  src = wk + (size_t)u*8; dh = g_wkhi; dl = g_wklo; }
    float4 a = *(const float4*)src;
    float4 b4 = *(const float4*)(src + 4);
    float vs[8] = {a.x, a.y, a.z, a.w, b4.x, b4.y, b4.z, b4.w};
    union { __nv_bfloat16 h[8]; int4 v; } hi, lo;
    #pragma unroll
    for (int i = 0; i < 8; i++) {
        hi.h[i] = __float2bfloat16(vs[i]);
        lo.h[i] = __float2bfloat16(vs[i] - __bfloat162float(hi.h[i]));
    }
    ((int4*)dh)[u] = hi.v;
    ((int4*)dl)[u] = lo.v;
}

// ---------------- Q/K projection via warp-mma (3-term split bf16) ----------------
#define PJ_STAGE 49152
#define PJ_XHI 0
#define PJ_XLO 16384
#define PJ_WHI 32768
#define PJ_WLO 40960
#define PJ_SM_TOTAL (2*PJ_STAGE)  // 96 KB

__device__ __forceinline__ void pj_copy_x(uint32_t sdst, const __nv_bfloat16* g0, int tid) {
    #pragma unroll
    for (int i = 0; i < 4; i++) {
        int u = tid + i*256;
        int row = u >> 3, cu = u & 7;
        uint32_t dst = sdst + row*128 + ((cu ^ (row & 7)) << 4);
        CP_ASYNC16(dst, (const char*)g0 + (size_t)row*1024 + cu*16);
    }
}
__device__ __forceinline__ void pj_copy_w(uint32_t sdst, const __nv_bfloat16* g0, int tid) {
    #pragma unroll
    for (int i = 0; i < 2; i++) {
        int u = tid + i*256;
        int row = u >> 3, cu = u & 7;
        uint32_t dst = sdst + row*128 + ((cu ^ (row & 7)) << 4);
        CP_ASYNC16(dst, (const char*)g0 + (size_t)row*1024 + cu*16);
    }
}

__global__ void __launch_bounds__(256, 2) proj_mma_kernel(const float* __restrict__ bias, int which) {
    extern __shared__ char smem[];
    uint32_t sb = smem_u32(smem);
    int tid = threadIdx.x;
    int w = tid >> 5, lane = tid & 31;
    int m0 = blockIdx.x * 128;
    int n0 = blockIdx.y * 64;

    const __nv_bfloat16* xhi = g_xhi + (size_t)m0*D;
    const __nv_bfloat16* xlo = g_xlo + (size_t)m0*D;
    const __nv_bfloat16* whi = (which ? g_wkhi : g_wqhi) + (size_t)n0*D;
    const __nv_bfloat16* wlo = (which ? g_wklo : g_wqlo) + (size_t)n0*D;
    float* outf = which ? g_K : g_Q;
    __nv_bfloat16* outh = which ? g_Khi : g_Qhi;

    pj_copy_x(sb + 0*PJ_STAGE + PJ_XHI, xhi, tid);
    pj_copy_x(sb + 0*PJ_STAGE + PJ_XLO, xlo, tid);
    pj_copy_w(sb + 0*PJ_STAGE + PJ_WHI, whi, tid);
    pj_copy_w(sb + 0*PJ_STAGE + PJ_WLO, wlo, tid);
    CP_COMMIT();
    pj_copy_x(sb + 1*PJ_STAGE + PJ_XHI, xhi + 64, tid);
    pj_copy_x(sb + 1*PJ_STAGE + PJ_XLO, xlo + 64, tid);
    pj_copy_w(sb + 1*PJ_STAGE + PJ_WHI, whi + 64, tid);
    pj_copy_w(sb + 1*PJ_STAGE + PJ_WLO, wlo + 64, tid);
    CP_COMMIT();

    float c[8][4];
    #pragma unroll
    for (int j = 0; j < 8; j++)
        #pragma unroll
        for (int r = 0; r < 4; r++) c[j][r] = 0.f;

    int row16 = lane & 15;
    int half = lane >> 4;
    int bi = lane >> 3;
    int br = lane & 7;

    #pragma unroll 1
    for (int kt = 0; kt < 8; kt++) {
        CP_WAIT1();
        __syncthreads();
        uint32_t st = sb + (kt & 1)*PJ_STAGE;

        uint32_t aHi[4][4], aLo[4][4];
        {
            uint32_t rowoff = (uint32_t)(w*16 + row16) * 128;
            #pragma unroll
            for (int ks = 0; ks < 4; ks++) {
                uint32_t unit = (uint32_t)(ks*2 + half);
                uint32_t off = rowoff + ((unit ^ (row16 & 7)) << 4);
                ldsm_x4(aHi[ks][0], aHi[ks][1], aHi[ks][2], aHi[ks][3], st + PJ_XHI + off);
                ldsm_x4(aLo[ks][0], aLo[ks][1], aLo[ks][2], aLo[ks][3], st + PJ_XLO + off);
            }
        }

        #pragma unroll
        for (int j = 0; j < 8; j++) {
            int row = j*8 + br;
            uint32_t rowoff = (uint32_t)row * 128;
            uint32_t sw0 = ((uint32_t)(bi    ) ^ (row & 7)) << 4;
            uint32_t sw1 = ((uint32_t)(bi + 4) ^ (row & 7)) << 4;
            uint32_t bh0,bh1,bh2,bh3,bh4,bh5,bh6,bh7;
            uint32_t bl0,bl1,bl2,bl3,bl4,bl5,bl6,bl7;
            ldsm_x4(bh0,bh1,bh2,bh3, st + PJ_WHI + rowoff + sw0);
            ldsm_x4(bh4,bh5,bh6,bh7, st + PJ_WHI + rowoff + sw1);
            ldsm_x4(bl0,bl1,bl2,bl3, st + PJ_WLO + rowoff + sw0);
            ldsm_x4(bl4,bl5,bl6,bl7, st + PJ_WLO + rowoff + sw1);

            mma_bf16(c[j][0],c[j][1],c[j][2],c[j][3], aHi[0][0],aHi[0][1],aHi[0][2],aHi[0][3], bh0,bh1);
            mma_bf16(c[j][0],c[j][1],c[j][2],c[j][3], aHi[1][0],aHi[1][1],aHi[1][2],aHi[1][3], bh2,bh3);
            mma_bf16(c[j][0],c[j][1],c[j][2],c[j][3], aHi[2][0],aHi[2][1],aHi[2][2],aHi[2][3], bh4,bh5);
            mma_bf16(c[j][0],c[j][1],c[j][2],c[j][3], aHi[3][0],aHi[3][1],aHi[3][2],aHi[3][3], bh6,bh7);
            mma_bf16(c[j][0],c[j][1],c[j][2],c[j][3], aHi[0][0],aHi[0][1],aHi[0][2],aHi[0][3], bl0,bl1);
            mma_bf16(c[j][0],c[j][1],c[j][2],c[j][3], aHi[1][0],aHi[1][1],aHi[1][2],aHi[1][3], bl2,bl3);
            mma_bf16(c[j][0],c[j][1],c[j][2],c[j][3], aHi[2][0],aHi[2][1],aHi[2][2],aHi[2][3], bl4,bl5);
            mma_bf16(c[j][0],c[j][1],c[j][2],c[j][3], aHi[3][0],aHi[3][1],aHi[3][2],aHi[3][3], bl6,bl7);
            mma_bf16(c[j][0],c[j][1],c[j][2],c[j][3], aLo[0][0],aLo[0][1],aLo[0][2],aLo[0][3], bh0,bh1);
            mma_bf16(c[j][0],c[j][1],c[j][2],c[j][3], aLo[1][0],aLo[1][1],aLo[1][2],aLo[1][3], bh2,bh3);
            mma_bf16(c[j][0],c[j][1],c[j][2],c[j][3], aLo[2][0],aLo[2][1],aLo[2][2],aLo[2][3], bh4,bh5);
            mma_bf16(c[j][0],c[j][1],c[j][2],c[j][3], aLo[3][0],aLo[3][1],aLo[3][2],aLo[3][3], bh6,bh7);
        }
        __syncthreads();
        if (kt + 2 < 8) {
            uint32_t st2 = sb + (kt & 1)*PJ_STAGE;
            int koff = (kt + 2) * 64;
            pj_copy_x(st2 + PJ_XHI, xhi + koff, tid);
            pj_copy_x(st2 + PJ_XLO, xlo + koff, tid);
            pj_copy_w(st2 + PJ_WHI, whi + koff, tid);
            pj_copy_w(st2 + PJ_WLO, wlo + koff, tid);
        }
        CP_COMMIT();
    }

    int r0 = m0 + w*16 + (lane >> 2);
    #pragma unroll
    for (int j = 0; j < 8; j++) {
        int n = n0 + j*8 + (lane & 3)*2;
        int h = n >> 6, k = n & 63;
        float b0 = bias[n], b1 = bias[n+1];
        #pragma unroll
        for (int rr = 0; rr < 2; rr++) {
            int m = r0 + rr*8;
            int b_ = m >> 11, s = m & (S-1);
            size_t idx = (((size_t)(b_*H + h)*S + s)*DK) + k;
            float v0 = c[j][rr*2+0] + b0;
            float v1 = c[j][rr*2+1] + b1;
            *(float2*)(outf + idx) = make_float2(v0, v1);
            union { __nv_bfloat16 h2[2]; uint32_t u; } ph;
            ph.h2[0] = __float2bfloat16(v0);
            ph.h2[1] = __float2bfloat16(v1);
            *(uint32_t*)(outh + idx) = ph.u;
        }
    }
}

// ---------------- scores: hi-only QK^T, packed (value|index) max ----------------
#define SQ 0
#define SKB 16384
#define SK_ST 16384
#define SM2_TOTAL (SKB + 2*SK_ST)   // 48 KB

__device__ __forceinline__ void copy_tile128(uint32_t sdst, const __nv_bfloat16* gsrc, int tid) {
    #pragma unroll
    for (int i = 0; i < 8; i++) {
        int u = tid + i*128;
        int row = u >> 3, cu = u & 7;
        uint32_t dst = sdst + row*128 + ((cu ^ (row & 7)) << 4);
        CP_ASYNC16(dst, (const char*)gsrc + (size_t)u*16);
    }
}

__device__ __forceinline__ float packv(float v, uint32_t col) {
    return __uint_as_float((__float_as_uint(v) & 0xFFFFF800u) | col);
}

__global__ void __launch_bounds__(128) scores_mma_kernel() {
    extern __shared__ char smem[];
    uint32_t sb = smem_u32(smem);
    int tid = threadIdx.x;
    int w = tid >> 5, lane = tid & 31;
    int bh = blockIdx.x;
    int qt = blockIdx.y;

    const __nv_bfloat16* qh_g = g_Qhi + (size_t)(bh*S + qt*128)*DK;
    const __nv_bfloat16* kh_g = g_Khi + (size_t)bh*S*DK;

    copy_tile128(sb + SQ, qh_g, tid);
    copy_tile128(sb + SKB + 0*SK_ST, kh_g, tid);
    CP_COMMIT();
    copy_tile128(sb + SKB + 1*SK_ST, kh_g + 128*DK, tid);
    CP_COMMIT();

    CP_WAIT1();
    __syncthreads();

    uint32_t aHi[2][4][4];
    {
        int row16 = lane & 15;
        int half = lane >> 4;
        #pragma unroll
        for (int rb = 0; rb < 2; rb++) {
            uint32_t rowoff = (uint32_t)(w*32 + rb*16 + row16) * 128;
            #pragma unroll
            for (int ks = 0; ks < 4; ks++) {
                uint32_t unit = (uint32_t)(ks*2 + half);
                uint32_t off = rowoff + ((unit ^ (row16 & 7)) << 4);
                ldsm_x4(aHi[rb][ks][0], aHi[rb][ks][1], aHi[rb][ks][2], aHi[rb][ks][3], sb + SQ + off);
            }
        }
    }

    float m1[4] = {-1e30f,-1e30f,-1e30f,-1e30f};
    int bi = lane >> 3;
    int br = lane & 7;

    #pragma unroll 1
    for (int kt = 0; kt < 16; kt++) {
        if (kt > 0) {
            CP_WAIT1();
            __syncthreads();
        }
        uint32_t kb = sb + SKB + (kt & 1)*SK_ST;

        #pragma unroll
        for (int t = 0; t < 16; t++) {
            int row = t*8 + br;
            uint32_t rowoff = (uint32_t)row * 128;
            uint32_t sw0 = ((uint32_t)(bi    ) ^ (row & 7)) << 4;
            uint32_t sw1 = ((uint32_t)(bi + 4) ^ (row & 7)) << 4;
            uint32_t b0,b1,b2,b3,b4,b5,b6,b7;
            ldsm_x4(b0,b1,b2,b3, kb + rowoff + sw0);
            ldsm_x4(b4,b5,b6,b7, kb + rowoff + sw1);
            uint32_t colb = (uint32_t)(kt*128 + t*8 + (lane & 3)*2);

            #pragma unroll
            for (int rb = 0; rb < 2; rb++) {
                float cA0=0.f,cA1=0.f,cA2=0.f,cA3=0.f;
                float cB0=0.f,cB1=0.f,cB2=0.f,cB3=0.f;
                mma_bf16(cA0,cA1,cA2,cA3, aHi[rb][0][0],aHi[rb][0][1],aHi[rb][0][2],aHi[rb][0][3], b0,b1);
                mma_bf16(cB0,cB1,cB2,cB3, aHi[rb][2][0],aHi[rb][2][1],aHi[rb][2][2],aHi[rb][2][3], b4,b5);
                mma_bf16(cA0,cA1,cA2,cA3, aHi[rb][1][0],aHi[rb][1][1],aHi[rb][1][2],aHi[rb][1][3], b2,b3);
                mma_bf16(cB0,cB1,cB2,cB3, aHi[rb][3][0],aHi[rb][3][1],aHi[rb][3][2],aHi[rb][3][3], b6,b7);
                float v0 = cA0 + cB0, v1 = cA1 + cB1, v2 = cA2 + cB2, v3 = cA3 + cB3;
                int sA = rb*2 + 0, sB = rb*2 + 1;
                m1[sA] = fmaxf(m1[sA], fmaxf(packv(v0, colb), packv(v1, colb + 1)));
                m1[sB] = fmaxf(m1[sB], fmaxf(packv(v2, colb), packv(v3, colb + 1)));
            }
        }
        __syncthreads();
        if (kt + 2 < 16) {
            copy_tile128(sb + SKB + (kt & 1)*SK_ST, kh_g + (size_t)(kt+2)*128*DK, tid);
        }
        CP_COMMIT();
    }

    #pragma unroll
    for (int s = 0; s < 4; s++) {
        float a1 = m1[s];
        #pragma unroll
        for (int off = 1; off < 4; off <<= 1)
            a1 = fmaxf(a1, __shfl_xor_sync(0xFFFFFFFFu, a1, off));
        if ((lane & 3) == 0) {
            int rb = s >> 1, half = s & 1;
            int r = qt*128 + w*32 + rb*16 + half*8 + (lane >> 2);
            g_sidx[bh*S + r] = (int)(__float_as_uint(a1) & 0x7FFu);
        }
    }
}

// ---------------- fused xsum-final + analytic sumK (= xsum . wk^T + S*bk) ----------------
__global__ void __launch_bounds__(512) xsum_sumk_kernel(const float* __restrict__ wk,
                                                        const float* __restrict__ bk) {
    __shared__ float xs[D];
    int b = blockIdx.x, tid = threadIdx.x;
    int lane = tid & 31, w = tid >> 5;
    {
        float acc = 0.f;
        #pragma unroll 8
        for (int sc = 0; sc < 32; sc++) acc += g_xpart[(size_t)(b*32+sc)*D + tid];
        xs[tid] = acc;
        g_xsum[b*D + tid] = acc;
    }
    __syncthreads();
    #pragma unroll 1
    for (int oo = 0; oo < 32; oo++) {
        int o = w*32 + oo;                   // 0..511 = h*64 + d
        const float* wr = wk + (size_t)o*D + lane;
        float acc = 0.f;
        #pragma unroll
        for (int k = 0; k < 16; k++) acc += xs[lane + k*32] * wr[k*32];
        #pragma unroll
        for (int off = 16; off > 0; off >>= 1) acc += __shfl_xor_sync(0xFFFFFFFFu, acc, off);
        if (lane == 0) {
            int h = o >> 6, d = o & 63;
            g_sumK[(b*H + h)*DK + d] = acc + (float)S * bk[o];
        }
    }
}

// ---------------- fixup: exact mean + exact dot at argmax -> sparsity ----------------
__global__ void __launch_bounds__(256) fixup_kernel() {
    int w = threadIdx.x >> 5, lane = threadIdx.x & 31;
    int g = blockIdx.x*8 + w;
    int bh = g >> 11;
    float q0 = g_Q[(size_t)g*DK + 2*lane];
    float q1 = g_Q[(size_t)g*DK + 2*lane + 1];
    float md = q0*g_sumK[bh*DK + 2*lane] + q1*g_sumK[bh*DK + 2*lane + 1];
    int idx = g_sidx[g];
    const float* kr = g_K + ((size_t)bh*S + idx)*DK;
    float e = q0*kr[2*lane] + q1*kr[2*lane + 1];
    #pragma unroll
    for (int off = 16; off > 0; off >>= 1) {
        md += __shfl_xor_sync(0xFFFFFFFFu, md, off);
        e  += __shfl_xor_sync(0xFFFFFFFFu, e,  off);
    }
    if (lane == 0) {
        float inv_log = 1.0f / logf((float)S);
        g_spars[g] = md * (1.0f/(8.0f*(float)S)) - e * 0.125f * inv_log;
    }
}

// ---------------- top-53 phase 1: per-256-slice candidates ----------------
__global__ void __launch_bounds__(64) topk_part_kernel() {
    __shared__ float vals[256];
    __shared__ float wmv[2];
    __shared__ int   wmi[2];
    int blk = blockIdx.x;
    int bh = blk >> 3, sl = blk & 7;
    int tid = threadIdx.x, lane = tid & 31, w = tid >> 5;
    int base = bh*S + sl*256;
    #pragma unroll
    for (int k = 0; k < 4; k++) vals[tid + k*64] = g_spars[base + tid + k*64];
    __syncthreads();
    for (int it = 0; it < U; it++) {
        float best = -1e30f; int bidx = 256;
        #pragma unroll
        for (int k = 0; k < 4; k++) {
            int i = tid + k*64;
            float v = vals[i];
            if (v > best || (v == best && i < bidx)) { best = v; bidx = i; }
        }
        #pragma unroll
        for (int off = 16; off > 0; off >>= 1) {
            float v2 = __shfl_down_sync(0xFFFFFFFFu, best, off);
            int i2 = __shfl_down_sync(0xFFFFFFFFu, bidx, off);
            if (v2 > best || (v2 == best && i2 < bidx)) { best = v2; bidx = i2; }
        }
        if (lane == 0) { wmv[w] = best; wmi[w] = bidx; }
        __syncthreads();
        if (tid == 0) {
            float m = wmv[0]; int mi = wmi[0];
            if (wmv[1] > m || (wmv[1] == m && wmi[1] < mi)) { m = wmv[1]; mi = wmi[1]; }
            g_candv[(bh*8 + sl)*U + it] = m;
            g_candi[(bh*8 + sl)*U + it] = sl*256 + mi;
            vals[mi] = -1e30f;
        }
        __syncthreads();
    }
}

// ---------------- top-53 phase 2: merge 8*53 candidates (one warp per bh) ----------------
__global__ void __launch_bounds__(32) topk_final_kernel() {
    __shared__ float vals[448];
    __shared__ int   idxs[448];
    int bh = blockIdx.x, lane = threadIdx.x;
    for (int i = lane; i < 8*U; i += 32) {
        vals[i] = g_candv[bh*8*U + i];
        idxs[i] = g_candi[bh*8*U + i];
    }
    for (int i = 8*U + lane; i < 448; i += 32) { vals[i] = -1e30f; idxs[i] = 1 << 30; }
    __syncwarp();
    for (int it = 0; it < U; it++) {
        float best = -1e30f; int bidx = 1 << 30, bpos = 0;
        #pragma unroll
        for (int k = 0; k < 14; k++) {
            int i = lane + k*32;
            float v = vals[i]; int gi = idxs[i];
            if (v > best || (v == best && gi < bidx)) { best = v; bidx = gi; bpos = i; }
        }
        #pragma unroll
        for (int off = 16; off > 0; off >>= 1) {
            float v2 = __shfl_down_sync(0xFFFFFFFFu, best, off);
            int i2 = __shfl_down_sync(0xFFFFFFFFu, bidx, off);
            int p2 = __shfl_down_sync(0xFFFFFFFFu, bpos, off);
            if (v2 > best || (v2 == best && i2 < bidx)) { best = v2; bidx = i2; bpos = p2; }
        }
        if (lane == 0) {
            g_topidx[bh*U + it] = bidx;
            vals[bpos] = -1e30f;
        }
        __syncwarp();
    }
}

// ---------------- fused meanV + ybase ----------------
__global__ void __launch_bounds__(512) meanv_ybase_kernel(
        const float* __restrict__ wv, const float* __restrict__ bv,
        const float* __restrict__ wo, const float* __restrict__ bo) {
    __shared__ float xs[D];
    __shared__ float mv[D];
    int b = blockIdx.x, tid = threadIdx.x;
    int lane = tid & 31, w = tid >> 5;
    xs[tid] = g_xsum[b*D + tid];
    __syncthreads();
    #pragma unroll 1
    for (int oo = 0; oo < 32; oo++) {
        int o = w*32 + oo;
        const float* wr = wv + (size_t)o*D + lane;
        float acc = 0.f;
        #pragma unroll
        for (int k = 0; k < 16; k++) acc += xs[lane + k*32] * wr[k*32];
        #pragma unroll
        for (int off = 16; off > 0; off >>= 1) acc += __shfl_xor_sync(0xFFFFFFFFu, acc, off);
        if (lane == 0) {
            float m = acc * (1.0f/(float)S) + bv[o];
            mv[o] = m;
            g_meanV[b*D + o] = m;
        }
    }
    __syncthreads();
    #pragma unroll 1
    for (int oo = 0; oo < 32; oo++) {
        int o = w*32 + oo;
        const float* wr = wo + (size_t)o*D + lane;
        float acc = 0.f;
        #pragma unroll
        for (int k = 0; k < 16; k++) acc += mv[lane + k*32] * wr[k*32];
        #pragma unroll
        for (int off = 16; off > 0; off >>= 1) acc += __shfl_xor_sync(0xFFFFFFFFu, acc, off);
        if (lane == 0) g_ybase[b*D + o] = acc + bo[o];
    }
}

// ---------------- corrections: one block per (b,h) ----------------
__global__ void __launch_bounds__(256) corr_kernel(const float* __restrict__ x,
                                                   const float* __restrict__ wv,
                                                   const float* __restrict__ bv) {
    __shared__ float sbuf[64*65 + 56*65];
    __shared__ int   s_idx[56];
    __shared__ float s_v[56];
    int bh = blockIdx.x;
    int b = bh / H, h = bh % H;
    int tid = threadIdx.x;
    if (tid < U) s_idx[tid] = g_topidx[bh*U + tid];
    __syncthreads();

    float* sq = sbuf;
    float* sk = sbuf + U*DK;
    for (int e = tid; e < U*DK; e += 256) sq[e] = g_Q[(size_t)bh*S*DK + e];
    for (int e = tid; e < U*DK; e += 256) {
        int i = e >> 6, d = e & 63;
        sk[e] = g_K[((size_t)bh*S + s_idx[i])*DK + d];
    }
    __syncthreads();
    if (tid < U) {
        float acc = 0.f;
        #pragma unroll 8
        for (int d = 0; d < DK; d++) acc += sq[tid*DK + d] * sk[tid*DK + d];
        s_v[tid] = acc * 0.125f;
    }
    __syncthreads();

    float* wvs = sbuf;
    float* xjs = sbuf + 64*65;
    int ci = tid & 15, ri = tid >> 4;
    float acc[4][4] = {};
    for (int dt = 0; dt < 8; dt++) {
        __syncthreads();
        for (int e = tid; e < 64*64; e += 256) {
            int r = e >> 6, c2 = e & 63;
            wvs[r*65 + c2] = wv[((size_t)(h*64 + r))*D + dt*64 + c2];
        }
        for (int e = tid; e < 56*64; e += 256) {
            int i = e >> 6, c2 = e & 63;
            xjs[i*65 + c2] = (i < U) ? x[((size_t)b*S + s_idx[i])*D + dt*64 + c2] : 0.f;
        }
        __syncthreads();
        if (ri < 14) {
            #pragma unroll 4
            for (int dd = 0; dd < 64; dd++) {
                float xv0 = xjs[(ri*4+0)*65 + dd];
                float xv1 = xjs[(ri*4+1)*65 + dd];
                float xv2 = xjs[(ri*4+2)*65 + dd];
                float xv3 = xjs[(ri*4+3)*65 + dd];
                float w0 = wvs[(ci*4+0)*65 + dd];
                float w1 = wvs[(ci*4+1)*65 + dd];
                float w2 = wvs[(ci*4+2)*65 + dd];
                float w3 = wvs[(ci*4+3)*65 + dd];
                acc[0][0] += xv0*w0; acc[0][1] += xv0*w1; acc[0][2] += xv0*w2; acc[0][3] += xv0*w3;
                acc[1][0] += xv1*w0; acc[1][1] += xv1*w1; acc[1][2] += xv1*w2; acc[1][3] += xv1*w3;
                acc[2][0] += xv2*w0; acc[2][1] += xv2*w1; acc[2][2] += xv2*w2; acc[2][3] += xv2*w3;
                acc[3][0] += xv3*w0; acc[3][1] += xv3*w1; acc[3][2] += xv3*w2; acc[3][3] += xv3*w3;
            }
        }
    }

    if (ri < 14) {
        #pragma unroll
        for (int r = 0; r < 4; r++) {
            int i = ri*4 + r;
            if (i >= U) continue;
            float ev = expf(s_v[i]);
            float em1 = ev - 1.0f;
            float Z = ev + (float)(S - 1);
            #pragma unroll
            for (int c2 = 0; c2 < 4; c2++) {
                int col = ci*4 + c2;
                float Vj = acc[r][c2] + bv[h*64 + col];
                float mvv = g_meanV[b*D + h*64 + col];
                g_outcat[((size_t)(b*U + i))*D + h*64 + col] = ((float)S * mvv + em1 * Vj) / Z;
            }
        }
    }
}

// ---------------- out-projection for the 212 corrected rows ----------------
__global__ void outproj_kernel(const float* __restrict__ wo, const float* __restrict__ bo,
                               float* __restrict__ y) {
    __shared__ float As[32][68];
    __shared__ float Bs[32][68];
    int tid = threadIdx.x;
    int tx = tid & 15, ty = tid >> 4;
    int m0 = blockIdx.x * 64;
    int n0 = blockIdx.y * 64;
    float acc[4][4] = {};
    for (int d0 = 0; d0 < D; d0 += 32) {
        #pragma unroll
        for (int i = 0; i < 2; i++) {
            int e = tid + i*256;
            int row = e >> 3;
            int c4 = e & 7;
            float4 v = make_float4(0.f, 0.f, 0.f, 0.f);
            if (m0 + row < B*U)
                v = *(const float4*)(g_outcat + (size_t)(m0+row)*D + d0 + c4*4);
            As[c4*4+0][row] = v.x; As[c4*4+1][row] = v.y;
            As[c4*4+2][row] = v.z; As[c4*4+3][row] = v.w;
            float4 u = *(const float4*)(wo + (size_t)(n0+row)*D + d0 + c4*4);
            Bs[c4*4+0][row] = u.x; Bs[c4*4+1][row] = u.y;
            Bs[c4*4+2][row] = u.z; Bs[c4*4+3][row] = u.w;
        }
        __syncthreads();
        #pragma unroll
        for (int kk = 0; kk < 32; kk++) {
            float4 a = *(const float4*)&As[kk][tx*4];
            float4 bv4 = *(const float4*)&Bs[kk][ty*4];
            float av[4] = {a.x, a.y, a.z, a.w};
            float bw[4] = {bv4.x, bv4.y, bv4.z, bv4.w};
            #pragma unroll
            for (int i = 0; i < 4; i++)
                #pragma unroll
                for (int j = 0; j < 4; j++)
                    acc[i][j] += av[i] * bw[j];
        }
        __syncthreads();
    }
    #pragma unroll
    for (int i = 0; i < 4; i++) {
        int m = m0 + tx*4 + i;
        if (m < B*U) {
            int b = m / U, s = m % U;
            float* op = y + ((size_t)b*S + s)*D + n0 + ty*4;
            #pragma unroll
            for (int j = 0; j < 4; j++)
                op[j] = acc[i][j] + bo[n0 + ty*4 + j];
        }
    }
}

// ---------------- broadcast the uniform rows (s >= U) ----------------
__global__ void bcast_kernel(float* __restrict__ y) {
    int id = blockIdx.x * blockDim.x + threadIdx.x;
    const int per_b = (S - U) * (D/4);
    const int total = B * per_b;
    if (id >= total) return;
    int b = id / per_b;
    int r = id % per_b;
    int s = U + r / (D/4);
    int d4 = r % (D/4);
    float4 v = *(const float4*)(g_ybase + b*D + d4*4);
    *(float4*)(y + ((size_t)b*S + s)*D + d4*4) = v;
}

extern "C" void kernel_launch(void* const* d_in, const int* in_sizes, int n_in,
                              void* d_out, int out_size) {
    const float* x  = (const float*)d_in[0];
    const float* wq = (const float*)d_in[1];
    const float* bq = (const float*)d_in[2];
    const float* wk = (const float*)d_in[3];
    const float* bk = (const float*)d_in[4];
    const float* wv = (const float*)d_in[5];
    const float* bv = (const float*)d_in[6];
    const float* wo = (const float*)d_in[7];
    const float* bo = (const float*)d_in[8];
    float* y = (float*)d_out;

    cudaFuncSetAttribute(scores_mma_kernel, cudaFuncAttributeMaxDynamicSharedMemorySize, SM2_TOTAL);
    cudaFuncSetAttribute(proj_mma_kernel, cudaFuncAttributeMaxDynamicSharedMemorySize, PJ_SM_TOTAL);

    {
        const int total = XU + 2*WU;
        convert_xw_kernel<<<(total + 255)/256, 256>>>(x, wq, wk);          // u1
    }

    dim3 pg(B*S/128, D/64);
    proj_mma_kernel<<<pg, 256, PJ_SM_TOTAL>>>(bq, 0);                      // u2

    sumx_part_kernel<<<B*32, 512>>>(x);                                    // u3

    proj_mma_kernel<<<pg, 256, PJ_SM_TOTAL>>>(bk, 1);                      // u4 <- ncu (projK)

    dim3 sg(BH, 16);
    scores_mma_kernel<<<sg, 128, SM2_TOTAL>>>();                           // u5

    xsum_sumk_kernel<<<B, 512>>>(wk, bk);                                  // u6

    fixup_kernel<<<BH*S/8, 256>>>();                                       // u7

    topk_part_kernel<<<BH*8, 64>>>();                                      // u8
    topk_final_kernel<<<BH, 32>>>();                                       // u9

    meanv_ybase_kernel<<<B, 512>>>(wv, bv, wo, bo);                        // u10

    corr_kernel<<<BH, 256>>>(x, wv, bv);                                   // u11

    dim3 og((B*U + 63)/64, D/64);
    outproj_kernel<<<og, 256>>>(wo, bo, y);                                // u12

    const int per_b = (S - U) * (D/4);
    bcast_kernel<<<(B*per_b + 255)/256, 256>>>(y);                         // u13
}

// round 14
// speedup vs baseline: 1.0372x; 1.0372x over previous
#include <cuda_runtime.h>
#include <cuda_bf16.h>
#include <math.h>
#include <stdint.h>

#define B 4
#define S 2048
#define D 512
#define H 8
#define DK 64
#define U 53
#define BH (B*H)

// ---------------- scratch ----------------
__device__ float g_Q[B*H*S*DK];       // fp32 [bh][s][k]
__device__ float g_K[B*H*S*DK];
__device__ float g_spars[B*H*S];
__device__ int   g_topidx[B*H*U];
__device__ float g_xpart[32*B*D];
__device__ float g_xsum[B*D];
__device__ float g_meanV[B*D];
__device__ float g_ybase[B*D];
__device__ float g_outcat[B*U*D];
__device__ float g_sumK[BH*DK];
__device__ int   g_sidx[BH*S];
// bf16 hi operands (written by proj epilogue)
__device__ __nv_bfloat16 g_Qhi[BH*S*DK];
__device__ __nv_bfloat16 g_Khi[BH*S*DK];
// split bf16 inputs for proj mma
__device__ __nv_bfloat16 g_xhi[B*S*D];
__device__ __nv_bfloat16 g_xlo[B*S*D];
__device__ __nv_bfloat16 g_wqhi[D*D];
__device__ __nv_bfloat16 g_wqlo[D*D];
__device__ __nv_bfloat16 g_wkhi[D*D];
__device__ __nv_bfloat16 g_wklo[D*D];

// ================= warp-mma helpers =================
__device__ __forceinline__ uint32_t smem_u32(const void* p) {
    uint32_t a;
    asm("{ .reg .u64 t; cvta.to.shared.u64 t, %1; cvt.u32.u64 %0, t; }" : "=r"(a) : "l"(p));
    return a;
}
__device__ __forceinline__ void ldsm_x4(uint32_t& r0, uint32_t& r1, uint32_t& r2, uint32_t& r3, uint32_t addr) {
    asm volatile("ldmatrix.sync.aligned.m8n8.x4.shared.b16 {%0,%1,%2,%3}, [%4];"
        : "=r"(r0), "=r"(r1), "=r"(r2), "=r"(r3) : "r"(addr));
}
__device__ __forceinline__ void mma_bf16(float& c0, float& c1, float& c2, float& c3,
                                         uint32_t a0, uint32_t a1, uint32_t a2, uint32_t a3,
                                         uint32_t b0, uint32_t b1) {
    asm volatile("mma.sync.aligned.m16n8k16.row.col.f32.bf16.bf16.f32 "
        "{%0,%1,%2,%3}, {%4,%5,%6,%7}, {%8,%9}, {%0,%1,%2,%3};"
        : "+f"(c0), "+f"(c1), "+f"(c2), "+f"(c3)
        : "r"(a0), "r"(a1), "r"(a2), "r"(a3), "r"(b0), "r"(b1));
}
#define CP_ASYNC16(dst, src) \
    asm volatile("cp.async.cg.shared.global [%0], [%1], 16;" :: "r"(dst), "l"(src))
#define CP_COMMIT() asm volatile("cp.async.commit_group;" ::: "memory")
#define CP_WAIT1()  asm volatile("cp.async.wait_group 1;" ::: "memory")

// ---------------- column sums of x (partials) ----------------
__global__ void sumx_part_kernel(const float* __restrict__ x) {
    int blk = blockIdx.x;
    int b = blk >> 5, sc = blk & 31;
    int d = threadIdx.x;
    const float* p = x + ((size_t)b*S + sc*64)*D + d;
    float acc = 0.f;
    #pragma unroll 8
    for (int s = 0; s < 64; s++) acc += p[(size_t)s*D];
    g_xpart[(size_t)blk*D + d] = acc;
}

// ---------------- fp32 -> split-bf16 for x, wq, wk ----------------
#define XU (B*S*D/8)
#define WU (D*D/8)
__global__ void convert_xw_kernel(const float* __restrict__ x, const float* __restrict__ wq,
                                  const float* __restrict__ wk) {
    int id = blockIdx.x * blockDim.x + threadIdx.x;
    if (id >= XU + 2*WU) return;
    const float* src;
    __nv_bfloat16 *dh, *dl;
    int u;
    if (id < XU)                { u = id;            src = x  + (size_t)u*8; dh = g_xhi;  dl = g_xlo;  }
    else if (id < XU + WU)      { u = id - XU;       src = wq + (size_t)u*8; dh = g_wqhi; dl = g_wqlo; }
    else                        { u = id - XU - WU;  src = wk + (size_t)u*8; dh = g_wkhi; dl = g_wklo; }
    float4 a = *(const float4*)src;
    float4 b4 = *(const float4*)(src + 4);
    float vs[8] = {a.x, a.y, a.z, a.w, b4.x, b4.y, b4.z, b4.w};
    union { __nv_bfloat16 h[8]; int4 v; } hi, lo;
    #pragma unroll
    for (int i = 0; i < 8; i++) {
        hi.h[i] = __float2bfloat16(vs[i]);
        lo.h[i] = __float2bfloat16(vs[i] - __bfloat162float(hi.h[i]));
    }
    ((int4*)dh)[u] = hi.v;
    ((int4*)dl)[u] = lo.v;
}

// ---------------- Q/K projection via warp-mma (3-term split bf16), z = which ----------------
#define PJ_STAGE 49152
#define PJ_XHI 0
#define PJ_XLO 16384
#define PJ_WHI 32768
#define PJ_WLO 40960
#define PJ_SM_TOTAL (2*PJ_STAGE)  // 96 KB

__device__ __forceinline__ void pj_copy_x(uint32_t sdst, const __nv_bfloat16* g0, int tid) {
    #pragma unroll
    for (int i = 0; i < 4; i++) {
        int u = tid + i*256;
        int row = u >> 3, cu = u & 7;
        uint32_t dst = sdst + row*128 + ((cu ^ (row & 7)) << 4);
        CP_ASYNC16(dst, (const char*)g0 + (size_t)row*1024 + cu*16);
    }
}
__device__ __forceinline__ void pj_copy_w(uint32_t sdst, const __nv_bfloat16* g0, int tid) {
    #pragma unroll
    for (int i = 0; i < 2; i++) {
        int u = tid + i*256;
        int row = u >> 3, cu = u & 7;
        uint32_t dst = sdst + row*128 + ((cu ^ (row & 7)) << 4);
        CP_ASYNC16(dst, (const char*)g0 + (size_t)row*1024 + cu*16);
    }
}

__global__ void __launch_bounds__(256, 2) proj_mma_kernel(const float* __restrict__ bq,
                                                          const float* __restrict__ bk) {
    extern __shared__ char smem[];
    uint32_t sb = smem_u32(smem);
    int tid = threadIdx.x;
    int w = tid >> 5, lane = tid & 31;
    int m0 = blockIdx.x * 128;
    int n0 = blockIdx.y * 64;
    int which = blockIdx.z;
    const float* bias = which ? bk : bq;

    const __nv_bfloat16* xhi = g_xhi + (size_t)m0*D;
    const __nv_bfloat16* xlo = g_xlo + (size_t)m0*D;
    const __nv_bfloat16* whi = (which ? g_wkhi : g_wqhi) + (size_t)n0*D;
    const __nv_bfloat16* wlo = (which ? g_wklo : g_wqlo) + (size_t)n0*D;
    float* outf = which ? g_K : g_Q;
    __nv_bfloat16* outh = which ? g_Khi : g_Qhi;

    pj_copy_x(sb + 0*PJ_STAGE + PJ_XHI, xhi, tid);
    pj_copy_x(sb + 0*PJ_STAGE + PJ_XLO, xlo, tid);
    pj_copy_w(sb + 0*PJ_STAGE + PJ_WHI, whi, tid);
    pj_copy_w(sb + 0*PJ_STAGE + PJ_WLO, wlo, tid);
    CP_COMMIT();
    pj_copy_x(sb + 1*PJ_STAGE + PJ_XHI, xhi + 64, tid);
    pj_copy_x(sb + 1*PJ_STAGE + PJ_XLO, xlo + 64, tid);
    pj_copy_w(sb + 1*PJ_STAGE + PJ_WHI, whi + 64, tid);
    pj_copy_w(sb + 1*PJ_STAGE + PJ_WLO, wlo + 64, tid);
    CP_COMMIT();

    float c[8][4];
    #pragma unroll
    for (int j = 0; j < 8; j++)
        #pragma unroll
        for (int r = 0; r < 4; r++) c[j][r] = 0.f;

    int row16 = lane & 15;
    int half = lane >> 4;
    int bi = lane >> 3;
    int br = lane & 7;

    #pragma unroll 1
    for (int kt = 0; kt < 8; kt++) {
        CP_WAIT1();
        __syncthreads();
        uint32_t st = sb + (kt & 1)*PJ_STAGE;

        uint32_t aHi[4][4], aLo[4][4];
        {
            uint32_t rowoff = (uint32_t)(w*16 + row16) * 128;
            #pragma unroll
            for (int ks = 0; ks < 4; ks++) {
                uint32_t unit = (uint32_t)(ks*2 + half);
                uint32_t off = rowoff + ((unit ^ (row16 & 7)) << 4);
                ldsm_x4(aHi[ks][0], aHi[ks][1], aHi[ks][2], aHi[ks][3], st + PJ_XHI + off);
                ldsm_x4(aLo[ks][0], aLo[ks][1], aLo[ks][2], aLo[ks][3], st + PJ_XLO + off);
            }
        }

        #pragma unroll
        for (int j = 0; j < 8; j++) {
            int row = j*8 + br;
            uint32_t rowoff = (uint32_t)row * 128;
            uint32_t sw0 = ((uint32_t)(bi    ) ^ (row & 7)) << 4;
            uint32_t sw1 = ((uint32_t)(bi + 4) ^ (row & 7)) << 4;
            uint32_t bh0,bh1,bh2,bh3,bh4,bh5,bh6,bh7;
            uint32_t bl0,bl1,bl2,bl3,bl4,bl5,bl6,bl7;
            ldsm_x4(bh0,bh1,bh2,bh3, st + PJ_WHI + rowoff + sw0);
            ldsm_x4(bh4,bh5,bh6,bh7, st + PJ_WHI + rowoff + sw1);
            ldsm_x4(bl0,bl1,bl2,bl3, st + PJ_WLO + rowoff + sw0);
            ldsm_x4(bl4,bl5,bl6,bl7, st + PJ_WLO + rowoff + sw1);

            mma_bf16(c[j][0],c[j][1],c[j][2],c[j][3], aHi[0][0],aHi[0][1],aHi[0][2],aHi[0][3], bh0,bh1);
            mma_bf16(c[j][0],c[j][1],c[j][2],c[j][3], aHi[1][0],aHi[1][1],aHi[1][2],aHi[1][3], bh2,bh3);
            mma_bf16(c[j][0],c[j][1],c[j][2],c[j][3], aHi[2][0],aHi[2][1],aHi[2][2],aHi[2][3], bh4,bh5);
            mma_bf16(c[j][0],c[j][1],c[j][2],c[j][3], aHi[3][0],aHi[3][1],aHi[3][2],aHi[3][3], bh6,bh7);
            mma_bf16(c[j][0],c[j][1],c[j][2],c[j][3], aHi[0][0],aHi[0][1],aHi[0][2],aHi[0][3], bl0,bl1);
            mma_bf16(c[j][0],c[j][1],c[j][2],c[j][3], aHi[1][0],aHi[1][1],aHi[1][2],aHi[1][3], bl2,bl3);
            mma_bf16(c[j][0],c[j][1],c[j][2],c[j][3], aHi[2][0],aHi[2][1],aHi[2][2],aHi[2][3], bl4,bl5);
            mma_bf16(c[j][0],c[j][1],c[j][2],c[j][3], aHi[3][0],aHi[3][1],aHi[3][2],aHi[3][3], bl6,bl7);
            mma_bf16(c[j][0],c[j][1],c[j][2],c[j][3], aLo[0][0],aLo[0][1],aLo[0][2],aLo[0][3], bh0,bh1);
            mma_bf16(c[j][0],c[j][1],c[j][2],c[j][3], aLo[1][0],aLo[1][1],aLo[1][2],aLo[1][3], bh2,bh3);
            mma_bf16(c[j][0],c[j][1],c[j][2],c[j][3], aLo[2][0],aLo[2][1],aLo[2][2],aLo[2][3], bh4,bh5);
            mma_bf16(c[j][0],c[j][1],c[j][2],c[j][3], aLo[3][0],aLo[3][1],aLo[3][2],aLo[3][3], bh6,bh7);
        }
        __syncthreads();
        if (kt + 2 < 8) {
            uint32_t st2 = sb + (kt & 1)*PJ_STAGE;
            int koff = (kt + 2) * 64;
            pj_copy_x(st2 + PJ_XHI, xhi + koff, tid);
            pj_copy_x(st2 + PJ_XLO, xlo + koff, tid);
            pj_copy_w(st2 + PJ_WHI, whi + koff, tid);
            pj_copy_w(st2 + PJ_WLO, wlo + koff, tid);
        }
        CP_COMMIT();
    }

    int r0 = m0 + w*16 + (lane >> 2);
    #pragma unroll
    for (int j = 0; j < 8; j++) {
        int n = n0 + j*8 + (lane & 3)*2;
        int h = n >> 6, k = n & 63;
        float b0 = bias[n], b1 = bias[n+1];
        #pragma unroll
        for (int rr = 0; rr < 2; rr++) {
            int m = r0 + rr*8;
            int b_ = m >> 11, s = m & (S-1);
            size_t idx = (((size_t)(b_*H + h)*S + s)*DK) + k;
            float v0 = c[j][rr*2+0] + b0;
            float v1 = c[j][rr*2+1] + b1;
            *(float2*)(outf + idx) = make_float2(v0, v1);
            union { __nv_bfloat16 h2[2]; uint32_t u; } ph;
            ph.h2[0] = __float2bfloat16(v0);
            ph.h2[1] = __float2bfloat16(v1);
            *(uint32_t*)(outh + idx) = ph.u;
        }
    }
}

// ---------------- scores: hi-only QK^T, packed (value|index) max ----------------
#define SQ 0
#define SKB 16384
#define SK_ST 16384
#define SM2_TOTAL (SKB + 2*SK_ST)   // 48 KB

__device__ __forceinline__ void copy_tile128(uint32_t sdst, const __nv_bfloat16* gsrc, int tid) {
    #pragma unroll
    for (int i = 0; i < 8; i++) {
        int u = tid + i*128;
        int row = u >> 3, cu = u & 7;
        uint32_t dst = sdst + row*128 + ((cu ^ (row & 7)) << 4);
        CP_ASYNC16(dst, (const char*)gsrc + (size_t)u*16);
    }
}

__device__ __forceinline__ float packv(float v, uint32_t col) {
    return __uint_as_float((__float_as_uint(v) & 0xFFFFF800u) | col);
}

__global__ void __launch_bounds__(128) scores_mma_kernel() {
    extern __shared__ char smem[];
    uint32_t sb = smem_u32(smem);
    int tid = threadIdx.x;
    int w = tid >> 5, lane = tid & 31;
    int bh = blockIdx.x;
    int qt = blockIdx.y;

    const __nv_bfloat16* qh_g = g_Qhi + (size_t)(bh*S + qt*128)*DK;
    const __nv_bfloat16* kh_g = g_Khi + (size_t)bh*S*DK;

    copy_tile128(sb + SQ, qh_g, tid);
    copy_tile128(sb + SKB + 0*SK_ST, kh_g, tid);
    CP_COMMIT();
    copy_tile128(sb + SKB + 1*SK_ST, kh_g + 128*DK, tid);
    CP_COMMIT();

    CP_WAIT1();
    __syncthreads();

    uint32_t aHi[2][4][4];
    {
        int row16 = lane & 15;
        int half = lane >> 4;
        #pragma unroll
        for (int rb = 0; rb < 2; rb++) {
            uint32_t rowoff = (uint32_t)(w*32 + rb*16 + row16) * 128;
            #pragma unroll
            for (int ks = 0; ks < 4; ks++) {
                uint32_t unit = (uint32_t)(ks*2 + half);
                uint32_t off = rowoff + ((unit ^ (row16 & 7)) << 4);
                ldsm_x4(aHi[rb][ks][0], aHi[rb][ks][1], aHi[rb][ks][2], aHi[rb][ks][3], sb + SQ + off);
            }
        }
    }

    float m1[4] = {-1e30f,-1e30f,-1e30f,-1e30f};
    int bi = lane >> 3;
    int br = lane & 7;

    #pragma unroll 1
    for (int kt = 0; kt < 16; kt++) {
        if (kt > 0) {
            CP_WAIT1();
            __syncthreads();
        }
        uint32_t kb = sb + SKB + (kt & 1)*SK_ST;

        #pragma unroll
        for (int t = 0; t < 16; t++) {
            int row = t*8 + br;
            uint32_t rowoff = (uint32_t)row * 128;
            uint32_t sw0 = ((uint32_t)(bi    ) ^ (row & 7)) << 4;
            uint32_t sw1 = ((uint32_t)(bi + 4) ^ (row & 7)) << 4;
            uint32_t b0,b1,b2,b3,b4,b5,b6,b7;
            ldsm_x4(b0,b1,b2,b3, kb + rowoff + sw0);
            ldsm_x4(b4,b5,b6,b7, kb + rowoff + sw1);
            uint32_t colb = (uint32_t)(kt*128 + t*8 + (lane & 3)*2);

            #pragma unroll
            for (int rb = 0; rb < 2; rb++) {
                float cA0=0.f,cA1=0.f,cA2=0.f,cA3=0.f;
                float cB0=0.f,cB1=0.f,cB2=0.f,cB3=0.f;
                mma_bf16(cA0,cA1,cA2,cA3, aHi[rb][0][0],aHi[rb][0][1],aHi[rb][0][2],aHi[rb][0][3], b0,b1);
                mma_bf16(cB0,cB1,cB2,cB3, aHi[rb][2][0],aHi[rb][2][1],aHi[rb][2][2],aHi[rb][2][3], b4,b5);
                mma_bf16(cA0,cA1,cA2,cA3, aHi[rb][1][0],aHi[rb][1][1],aHi[rb][1][2],aHi[rb][1][3], b2,b3);
                mma_bf16(cB0,cB1,cB2,cB3, aHi[rb][3][0],aHi[rb][3][1],aHi[rb][3][2],aHi[rb][3][3], b6,b7);
                float v0 = cA0 + cB0, v1 = cA1 + cB1, v2 = cA2 + cB2, v3 = cA3 + cB3;
                int sA = rb*2 + 0, sB = rb*2 + 1;
                m1[sA] = fmaxf(m1[sA], fmaxf(packv(v0, colb), packv(v1, colb + 1)));
                m1[sB] = fmaxf(m1[sB], fmaxf(packv(v2, colb), packv(v3, colb + 1)));
            }
        }
        __syncthreads();
        if (kt + 2 < 16) {
            copy_tile128(sb + SKB + (kt & 1)*SK_ST, kh_g + (size_t)(kt+2)*128*DK, tid);
        }
        CP_COMMIT();
    }

    #pragma unroll
    for (int s = 0; s < 4; s++) {
        float a1 = m1[s];
        #pragma unroll
        for (int off = 1; off < 4; off <<= 1)
            a1 = fmaxf(a1, __shfl_xor_sync(0xFFFFFFFFu, a1, off));
        if ((lane & 3) == 0) {
            int rb = s >> 1, half = s & 1;
            int r = qt*128 + w*32 + rb*16 + half*8 + (lane >> 2);
            g_sidx[bh*S + r] = (int)(__float_as_uint(a1) & 0x7FFu);
        }
    }
}

// ---------------- fused xsum-final + analytic sumK (= xsum . wk^T + S*bk) ----------------
__global__ void __launch_bounds__(512) xsum_sumk_kernel(const float* __restrict__ wk,
                                                        const float* __restrict__ bk) {
    __shared__ float xs[D];
    int b = blockIdx.x, tid = threadIdx.x;
    int lane = tid & 31, w = tid >> 5;
    {
        float acc = 0.f;
        #pragma unroll 8
        for (int sc = 0; sc < 32; sc++) acc += g_xpart[(size_t)(b*32+sc)*D + tid];
        xs[tid] = acc;
        g_xsum[b*D + tid] = acc;
    }
    __syncthreads();
    #pragma unroll 1
    for (int oo = 0; oo < 32; oo++) {
        int o = w*32 + oo;                   // 0..511 = h*64 + d
        const float* wr = wk + (size_t)o*D + lane;
        float acc = 0.f;
        #pragma unroll
        for (int k = 0; k < 16; k++) acc += xs[lane + k*32] * wr[k*32];
        #pragma unroll
        for (int off = 16; off > 0; off >>= 1) acc += __shfl_xor_sync(0xFFFFFFFFu, acc, off);
        if (lane == 0) {
            int h = o >> 6, d = o & 63;
            g_sumK[(b*H + h)*DK + d] = acc + (float)S * bk[o];
        }
    }
}

// ---------------- fixup: exact mean + exact dot at argmax -> sparsity ----------------
__global__ void __launch_bounds__(256) fixup_kernel() {
    int w = threadIdx.x >> 5, lane = threadIdx.x & 31;
    int g = blockIdx.x*8 + w;
    int bh = g >> 11;
    float q0 = g_Q[(size_t)g*DK + 2*lane];
    float q1 = g_Q[(size_t)g*DK + 2*lane + 1];
    float md = q0*g_sumK[bh*DK + 2*lane] + q1*g_sumK[bh*DK + 2*lane + 1];
    int idx = g_sidx[g];
    const float* kr = g_K + ((size_t)bh*S + idx)*DK;
    float e = q0*kr[2*lane] + q1*kr[2*lane + 1];
    #pragma unroll
    for (int off = 16; off > 0; off >>= 1) {
        md += __shfl_xor_sync(0xFFFFFFFFu, md, off);
        e  += __shfl_xor_sync(0xFFFFFFFFu, e,  off);
    }
    if (lane == 0) {
        float inv_log = 1.0f / logf((float)S);
        g_spars[g] = md * (1.0f/(8.0f*(float)S)) - e * 0.125f * inv_log;
    }
}

// ---------------- iterative top-53 per (b,h) ----------------
__global__ void topk_kernel() {
    __shared__ float vals[S];
    __shared__ float wm[8];
    __shared__ int   wi[8];
    int bh = blockIdx.x, tid = threadIdx.x;
    int lane = tid & 31, wid = tid >> 5;
    for (int i = tid; i < S; i += 256) vals[i] = g_spars[bh*S + i];
    __syncthreads();
    for (int it = 0; it < U; it++) {
        float best = -1e30f; int bidx = S;
        #pragma unroll
        for (int k = 0; k < 8; k++) {
            int i = tid + k*256;
            float v = vals[i];
            if (v > best || (v == best && i < bidx)) { best = v; bidx = i; }
        }
        #pragma unroll
        for (int off = 16; off > 0; off >>= 1) {
            float v2 = __shfl_down_sync(0xFFFFFFFFu, best, off);
            int i2 = __shfl_down_sync(0xFFFFFFFFu, bidx, off);
            if (v2 > best || (v2 == best && i2 < bidx)) { best = v2; bidx = i2; }
        }
        if (lane == 0) { wm[wid] = best; wi[wid] = bidx; }
        __syncthreads();
        if (tid == 0) {
            float m = wm[0]; int mi = wi[0];
            #pragma unroll
            for (int t = 1; t < 8; t++)
                if (wm[t] > m || (wm[t] == m && wi[t] < mi)) { m = wm[t]; mi = wi[t]; }
            g_topidx[bh*U + it] = mi;
            vals[mi] = -1e30f;
        }
        __syncthreads();
    }
}

// ---------------- fused meanV + ybase ----------------
__global__ void __launch_bounds__(512) meanv_ybase_kernel(
        const float* __restrict__ wv, const float* __restrict__ bv,
        const float* __restrict__ wo, const float* __restrict__ bo) {
    __shared__ float xs[D];
    __shared__ float mv[D];
    int b = blockIdx.x, tid = threadIdx.x;
    int lane = tid & 31, w = tid >> 5;
    xs[tid] = g_xsum[b*D + tid];
    __syncthreads();
    #pragma unroll 1
    for (int oo = 0; oo < 32; oo++) {
        int o = w*32 + oo;
        const float* wr = wv + (size_t)o*D + lane;
        float acc = 0.f;
        #pragma unroll
        for (int k = 0; k < 16; k++) acc += xs[lane + k*32] * wr[k*32];
        #pragma unroll
        for (int off = 16; off > 0; off >>= 1) acc += __shfl_xor_sync(0xFFFFFFFFu, acc, off);
        if (lane == 0) {
            float m = acc * (1.0f/(float)S) + bv[o];
            mv[o] = m;
            g_meanV[b*D + o] = m;
        }
    }
    __syncthreads();
    #pragma unroll 1
    for (int oo = 0; oo < 32; oo++) {
        int o = w*32 + oo;
        const float* wr = wo + (size_t)o*D + lane;
        float acc = 0.f;
        #pragma unroll
        for (int k = 0; k < 16; k++) acc += mv[lane + k*32] * wr[k*32];
        #pragma unroll
        for (int off = 16; off > 0; off >>= 1) acc += __shfl_xor_sync(0xFFFFFFFFu, acc, off);
        if (lane == 0) g_ybase[b*D + o] = acc + bo[o];
    }
}

// ---------------- corrections: one block per (b,h) ----------------
__global__ void __launch_bounds__(256) corr_kernel(const float* __restrict__ x,
                                                   const float* __restrict__ wv,
                                                   const float* __restrict__ bv) {
    __shared__ float sbuf[64*65 + 56*65];
    __shared__ int   s_idx[56];
    __shared__ float s_v[56];
    int bh = blockIdx.x;
    int b = bh / H, h = bh % H;
    int tid = threadIdx.x;
    if (tid < U) s_idx[tid] = g_topidx[bh*U + tid];
    __syncthreads();

    float* sq = sbuf;
    float* sk = sbuf + U*DK;
    for (int e = tid; e < U*DK; e += 256) sq[e] = g_Q[(size_t)bh*S*DK + e];
    for (int e = tid; e < U*DK; e += 256) {
        int i = e >> 6, d = e & 63;
        sk[e] = g_K[((size_t)bh*S + s_idx[i])*DK + d];
    }
    __syncthreads();
    if (tid < U) {
        float acc = 0.f;
        #pragma unroll 8
        for (int d = 0; d < DK; d++) acc += sq[tid*DK + d] * sk[tid*DK + d];
        s_v[tid] = acc * 0.125f;
    }
    __syncthreads();

    float* wvs = sbuf;
    float* xjs = sbuf + 64*65;
    int ci = tid & 15, ri = tid >> 4;
    float acc[4][4] = {};
    for (int dt = 0; dt < 8; dt++) {
        __syncthreads();
        for (int e = tid; e < 64*64; e += 256) {
            int r = e >> 6, c2 = e & 63;
            wvs[r*65 + c2] = wv[((size_t)(h*64 + r))*D + dt*64 + c2];
        }
        for (int e = tid; e < 56*64; e += 256) {
            int i = e >> 6, c2 = e & 63;
            xjs[i*65 + c2] = (i < U) ? x[((size_t)b*S + s_idx[i])*D + dt*64 + c2] : 0.f;
        }
        __syncthreads();
        if (ri < 14) {
            #pragma unroll 4
            for (int dd = 0; dd < 64; dd++) {
                float xv0 = xjs[(ri*4+0)*65 + dd];
                float xv1 = xjs[(ri*4+1)*65 + dd];
                float xv2 = xjs[(ri*4+2)*65 + dd];
                float xv3 = xjs[(ri*4+3)*65 + dd];
                float w0 = wvs[(ci*4+0)*65 + dd];
                float w1 = wvs[(ci*4+1)*65 + dd];
                float w2 = wvs[(ci*4+2)*65 + dd];
                float w3 = wvs[(ci*4+3)*65 + dd];
                acc[0][0] += xv0*w0; acc[0][1] += xv0*w1; acc[0][2] += xv0*w2; acc[0][3] += xv0*w3;
                acc[1][0] += xv1*w0; acc[1][1] += xv1*w1; acc[1][2] += xv1*w2; acc[1][3] += xv1*w3;
                acc[2][0] += xv2*w0; acc[2][1] += xv2*w1; acc[2][2] += xv2*w2; acc[2][3] += xv2*w3;
                acc[3][0] += xv3*w0; acc[3][1] += xv3*w1; acc[3][2] += xv3*w2; acc[3][3] += xv3*w3;
            }
        }
    }

    if (ri < 14) {
        #pragma unroll
        for (int r = 0; r < 4; r++) {
            int i = ri*4 + r;
            if (i >= U) continue;
            float ev = expf(s_v[i]);
            float em1 = ev - 1.0f;
            float Z = ev + (float)(S - 1);
            #pragma unroll
            for (int c2 = 0; c2 < 4; c2++) {
                int col = ci*4 + c2;
                float Vj = acc[r][c2] + bv[h*64 + col];
                float mvv = g_meanV[b*D + h*64 + col];
                g_outcat[((size_t)(b*U + i))*D + h*64 + col] = ((float)S * mvv + em1 * Vj) / Z;
            }
        }
    }
}

// ---------------- out-projection for the 212 corrected rows ----------------
__global__ void outproj_kernel(const float* __restrict__ wo, const float* __restrict__ bo,
                               float* __restrict__ y) {
    __shared__ float As[32][68];
    __shared__ float Bs[32][68];
    int tid = threadIdx.x;
    int tx = tid & 15, ty = tid >> 4;
    int m0 = blockIdx.x * 64;
    int n0 = blockIdx.y * 64;
    float acc[4][4] = {};
    for (int d0 = 0; d0 < D; d0 += 32) {
        #pragma unroll
        for (int i = 0; i < 2; i++) {
            int e = tid + i*256;
            int row = e >> 3;
            int c4 = e & 7;
            float4 v = make_float4(0.f, 0.f, 0.f, 0.f);
            if (m0 + row < B*U)
                v = *(const float4*)(g_outcat + (size_t)(m0+row)*D + d0 + c4*4);
            As[c4*4+0][row] = v.x; As[c4*4+1][row] = v.y;
            As[c4*4+2][row] = v.z; As[c4*4+3][row] = v.w;
            float4 u = *(const float4*)(wo + (size_t)(n0+row)*D + d0 + c4*4);
            Bs[c4*4+0][row] = u.x; Bs[c4*4+1][row] = u.y;
            Bs[c4*4+2][row] = u.z; Bs[c4*4+3][row] = u.w;
        }
        __syncthreads();
        #pragma unroll
        for (int kk = 0; kk < 32; kk++) {
            float4 a = *(const float4*)&As[kk][tx*4];
            float4 bv4 = *(const float4*)&Bs[kk][ty*4];
            float av[4] = {a.x, a.y, a.z, a.w};
            float bw[4] = {bv4.x, bv4.y, bv4.z, bv4.w};
            #pragma unroll
            for (int i = 0; i < 4; i++)
                #pragma unroll
                for (int j = 0; j < 4; j++)
                    acc[i][j] += av[i] * bw[j];
        }
        __syncthreads();
    }
    #pragma unroll
    for (int i = 0; i < 4; i++) {
        int m = m0 + tx*4 + i;
        if (m < B*U) {
            int b = m / U, s = m % U;
            float* op = y + ((size_t)b*S + s)*D + n0 + ty*4;
            #pragma unroll
            for (int j = 0; j < 4; j++)
                op[j] = acc[i][j] + bo[n0 + ty*4 + j];
        }
    }
}

// ---------------- broadcast the uniform rows (s >= U) ----------------
__global__ void bcast_kernel(float* __restrict__ y) {
    int id = blockIdx.x * blockDim.x + threadIdx.x;
    const int per_b = (S - U) * (D/4);
    const int total = B * per_b;
    if (id >= total) return;
    int b = id / per_b;
    int r = id % per_b;
    int s = U + r / (D/4);
    int d4 = r % (D/4);
    float4 v = *(const float4*)(g_ybase + b*D + d4*4);
    *(float4*)(y + ((size_t)b*S + s)*D + d4*4) = v;
}

extern "C" void kernel_launch(void* const* d_in, const int* in_sizes, int n_in,
                              void* d_out, int out_size) {
    const float* x  = (const float*)d_in[0];
    const float* wq = (const float*)d_in[1];
    const float* bq = (const float*)d_in[2];
    const float* wk = (const float*)d_in[3];
    const float* bk = (const float*)d_in[4];
    const float* wv = (const float*)d_in[5];
    const float* bv = (const float*)d_in[6];
    const float* wo = (const float*)d_in[7];
    const float* bo = (const float*)d_in[8];
    float* y = (float*)d_out;

    cudaFuncSetAttribute(scores_mma_kernel, cudaFuncAttributeMaxDynamicSharedMemorySize, SM2_TOTAL);
    cudaFuncSetAttribute(proj_mma_kernel, cudaFuncAttributeMaxDynamicSharedMemorySize, PJ_SM_TOTAL);

    {
        const int total = XU + 2*WU;
        convert_xw_kernel<<<(total + 255)/256, 256>>>(x, wq, wk);          // u1
    }

    dim3 pg(B*S/128, D/64, 2);
    proj_mma_kernel<<<pg, 256, PJ_SM_TOTAL>>>(bq, bk);                     // u2

    sumx_part_kernel<<<B*32, 512>>>(x);                                    // u3

    dim3 sg(BH, 16);
    scores_mma_kernel<<<sg, 128, SM2_TOTAL>>>();                           // u4 <- ncu

    xsum_sumk_kernel<<<B, 512>>>(wk, bk);                                  // u5

    fixup_kernel<<<BH*S/8, 256>>>();                                       // u6

    topk_kernel<<<BH, 256>>>();                                            // u7

    meanv_ybase_kernel<<<B, 512>>>(wv, bv, wo, bo);                        // u8

    corr_kernel<<<BH, 256>>>(x, wv, bv);                                   // u9

    dim3 og((B*U + 63)/64, D/64);
    outproj_kernel<<<og, 256>>>(wo, bo, y);                                // u10

    const int per_b = (S - U) * (D/4);
    bcast_kernel<<<(B*per_b + 255)/256, 256>>>(y);                         // u11
}

// round 15
// speedup vs baseline: 1.2092x; 1.1658x over previous
#include <cuda_runtime.h>
#include <cuda_fp16.h>
#include <math.h>
#include <stdint.h>

#define B 4
#define S 2048
#define D 512
#define H 8
#define DK 64
#define U 53
#define BH (B*H)

// ---------------- scratch ----------------
__device__ float g_Q[B*H*S*DK];       // fp32 [bh][s][k]
__device__ float g_K[B*H*S*DK];
__device__ float g_spars[B*H*S];
__device__ int   g_topidx[B*H*U];
__device__ float g_xpart[32*B*D];
__device__ float g_xsum[B*D];
__device__ float g_meanV[B*D];
__device__ float g_ybase[B*D];
__device__ float g_outcat[B*U*D];
__device__ float g_sumK[BH*DK];
__device__ int   g_sidx[BH*S];
// fp16 operands
__device__ __half g_Qh[BH*S*DK];
__device__ __half g_Kh[BH*S*DK];
__device__ __half g_xh[B*S*D];
__device__ __half g_wqh[D*D];
__device__ __half g_wkh[D*D];

// ================= warp-mma helpers =================
__device__ __forceinline__ uint32_t smem_u32(const void* p) {
    uint32_t a;
    asm("{ .reg .u64 t; cvta.to.shared.u64 t, %1; cvt.u32.u64 %0, t; }" : "=r"(a) : "l"(p));
    return a;
}
__device__ __forceinline__ void ldsm_x4(uint32_t& r0, uint32_t& r1, uint32_t& r2, uint32_t& r3, uint32_t addr) {
    asm volatile("ldmatrix.sync.aligned.m8n8.x4.shared.b16 {%0,%1,%2,%3}, [%4];"
        : "=r"(r0), "=r"(r1), "=r"(r2), "=r"(r3) : "r"(addr));
}
__device__ __forceinline__ void mma_f16(float& c0, float& c1, float& c2, float& c3,
                                        uint32_t a0, uint32_t a1, uint32_t a2, uint32_t a3,
                                        uint32_t b0, uint32_t b1) {
    asm volatile("mma.sync.aligned.m16n8k16.row.col.f32.f16.f16.f32 "
        "{%0,%1,%2,%3}, {%4,%5,%6,%7}, {%8,%9}, {%0,%1,%2,%3};"
        : "+f"(c0), "+f"(c1), "+f"(c2), "+f"(c3)
        : "r"(a0), "r"(a1), "r"(a2), "r"(a3), "r"(b0), "r"(b1));
}
#define CP_ASYNC16(dst, src) \
    asm volatile("cp.async.cg.shared.global [%0], [%1], 16;" :: "r"(dst), "l"(src))
#define CP_COMMIT() asm volatile("cp.async.commit_group;" ::: "memory")
#define CP_WAIT1()  asm volatile("cp.async.wait_group 1;" ::: "memory")

// ---------------- column sums of x (partials) ----------------
__global__ void sumx_part_kernel(const float* __restrict__ x) {
    int blk = blockIdx.x;
    int b = blk >> 5, sc = blk & 31;
    int d = threadIdx.x;
    const float* p = x + ((size_t)b*S + sc*64)*D + d;
    float acc = 0.f;
    #pragma unroll 8
    for (int s = 0; s < 64; s++) acc += p[(size_t)s*D];
    g_xpart[(size_t)blk*D + d] = acc;
}

// ---------------- fp32 -> fp16 for x, wq, wk ----------------
#define XU (B*S*D/8)
#define WU (D*D/8)
__global__ void convert_xw_kernel(const float* __restrict__ x, const float* __restrict__ wq,
                                  const float* __restrict__ wk) {
    int id = blockIdx.x * blockDim.x + threadIdx.x;
    if (id >= XU + 2*WU) return;
    const float* src;
    __half* dh;
    int u;
    if (id < XU)                { u = id;            src = x  + (size_t)u*8; dh = g_xh;  }
    else if (id < XU + WU)      { u = id - XU;       src = wq + (size_t)u*8; dh = g_wqh; }
    else                        { u = id - XU - WU;  src = wk + (size_t)u*8; dh = g_wkh; }
    float4 a = *(const float4*)src;
    float4 b4 = *(const float4*)(src + 4);
    float vs[8] = {a.x, a.y, a.z, a.w, b4.x, b4.y, b4.z, b4.w};
    union { __half h[8]; int4 v; } hv;
    #pragma unroll
    for (int i = 0; i < 8; i++) hv.h[i] = __float2half_rn(vs[i]);
    ((int4*)dh)[u] = hv.v;
}

// ---------------- Q/K projection via warp-mma (fp16), z = which ----------------
#define PJ_STAGE 24576          // x 16KB | w 8KB
#define PJ_XH 0
#define PJ_WH 16384
#define PJ_SM_TOTAL (2*PJ_STAGE)  // 48 KB

__device__ __forceinline__ void pj_copy_x(uint32_t sdst, const __half* g0, int tid) {
    #pragma unroll
    for (int i = 0; i < 4; i++) {
        int u = tid + i*256;             // 1024 units (128 rows x 8)
        int row = u >> 3, cu = u & 7;
        uint32_t dst = sdst + row*128 + ((cu ^ (row & 7)) << 4);
        CP_ASYNC16(dst, (const char*)g0 + (size_t)row*1024 + cu*16);
    }
}
__device__ __forceinline__ void pj_copy_w(uint32_t sdst, const __half* g0, int tid) {
    #pragma unroll
    for (int i = 0; i < 2; i++) {
        int u = tid + i*256;             // 512 units (64 rows x 8)
        int row = u >> 3, cu = u & 7;
        uint32_t dst = sdst + row*128 + ((cu ^ (row & 7)) << 4);
        CP_ASYNC16(dst, (const char*)g0 + (size_t)row*1024 + cu*16);
    }
}

__global__ void __launch_bounds__(256) proj_mma_kernel(const float* __restrict__ bq,
                                                       const float* __restrict__ bk) {
    extern __shared__ char smem[];
    uint32_t sb = smem_u32(smem);
    int tid = threadIdx.x;
    int w = tid >> 5, lane = tid & 31;
    int m0 = blockIdx.x * 128;
    int n0 = blockIdx.y * 64;
    int which = blockIdx.z;
    const float* bias = which ? bk : bq;

    const __half* xh = g_xh + (size_t)m0*D;
    const __half* wh = (which ? g_wkh : g_wqh) + (size_t)n0*D;
    float* outf = which ? g_K : g_Q;
    __half* outh = which ? g_Kh : g_Qh;

    pj_copy_x(sb + 0*PJ_STAGE + PJ_XH, xh, tid);
    pj_copy_w(sb + 0*PJ_STAGE + PJ_WH, wh, tid);
    CP_COMMIT();
    pj_copy_x(sb + 1*PJ_STAGE + PJ_XH, xh + 64, tid);
    pj_copy_w(sb + 1*PJ_STAGE + PJ_WH, wh + 64, tid);
    CP_COMMIT();

    float c[8][4];
    #pragma unroll
    for (int j = 0; j < 8; j++)
        #pragma unroll
        for (int r = 0; r < 4; r++) c[j][r] = 0.f;

    int row16 = lane & 15;
    int half = lane >> 4;
    int bi = lane >> 3;
    int br = lane & 7;

    #pragma unroll 1
    for (int kt = 0; kt < 8; kt++) {
        CP_WAIT1();
        __syncthreads();
        uint32_t st = sb + (kt & 1)*PJ_STAGE;

        uint32_t aF[4][4];
        {
            uint32_t rowoff = (uint32_t)(w*16 + row16) * 128;
            #pragma unroll
            for (int ks = 0; ks < 4; ks++) {
                uint32_t unit = (uint32_t)(ks*2 + half);
                uint32_t off = rowoff + ((unit ^ (row16 & 7)) << 4);
                ldsm_x4(aF[ks][0], aF[ks][1], aF[ks][2], aF[ks][3], st + PJ_XH + off);
            }
        }

        #pragma unroll
        for (int j = 0; j < 8; j++) {
            int row = j*8 + br;
            uint32_t rowoff = (uint32_t)row * 128;
            uint32_t sw0 = ((uint32_t)(bi    ) ^ (row & 7)) << 4;
            uint32_t sw1 = ((uint32_t)(bi + 4) ^ (row & 7)) << 4;
            uint32_t b0,b1,b2,b3,b4,b5,b6,b7;
            ldsm_x4(b0,b1,b2,b3, st + PJ_WH + rowoff + sw0);
            ldsm_x4(b4,b5,b6,b7, st + PJ_WH + rowoff + sw1);

            mma_f16(c[j][0],c[j][1],c[j][2],c[j][3], aF[0][0],aF[0][1],aF[0][2],aF[0][3], b0,b1);
            mma_f16(c[j][0],c[j][1],c[j][2],c[j][3], aF[1][0],aF[1][1],aF[1][2],aF[1][3], b2,b3);
            mma_f16(c[j][0],c[j][1],c[j][2],c[j][3], aF[2][0],aF[2][1],aF[2][2],aF[2][3], b4,b5);
            mma_f16(c[j][0],c[j][1],c[j][2],c[j][3], aF[3][0],aF[3][1],aF[3][2],aF[3][3], b6,b7);
        }
        __syncthreads();
        if (kt + 2 < 8) {
            uint32_t st2 = sb + (kt & 1)*PJ_STAGE;
            int koff = (kt + 2) * 64;
            pj_copy_x(st2 + PJ_XH, xh + koff, tid);
            pj_copy_w(st2 + PJ_WH, wh + koff, tid);
        }
        CP_COMMIT();
    }

    int r0 = m0 + w*16 + (lane >> 2);
    #pragma unroll
    for (int j = 0; j < 8; j++) {
        int n = n0 + j*8 + (lane & 3)*2;
        int h = n >> 6, k = n & 63;
        float b0 = bias[n], b1 = bias[n+1];
        #pragma unroll
        for (int rr = 0; rr < 2; rr++) {
            int m = r0 + rr*8;
            int b_ = m >> 11, s = m & (S-1);
            size_t idx = (((size_t)(b_*H + h)*S + s)*DK) + k;
            float v0 = c[j][rr*2+0] + b0;
            float v1 = c[j][rr*2+1] + b1;
            *(float2*)(outf + idx) = make_float2(v0, v1);
            union { __half h2[2]; uint32_t u; } ph;
            ph.h2[0] = __float2half_rn(v0);
            ph.h2[1] = __float2half_rn(v1);
            *(uint32_t*)(outh + idx) = ph.u;
        }
    }
}

// ---------------- scores: fp16 QK^T, packed (value|index) max ----------------
#define SQ 0
#define SKB 16384
#define SK_ST 16384
#define SM2_TOTAL (SKB + 2*SK_ST)   // 48 KB

__device__ __forceinline__ void copy_tile128(uint32_t sdst, const __half* gsrc, int tid) {
    #pragma unroll
    for (int i = 0; i < 8; i++) {
        int u = tid + i*128;
        int row = u >> 3, cu = u & 7;
        uint32_t dst = sdst + row*128 + ((cu ^ (row & 7)) << 4);
        CP_ASYNC16(dst, (const char*)gsrc + (size_t)u*16);
    }
}

__device__ __forceinline__ float packv(float v, uint32_t col) {
    return __uint_as_float((__float_as_uint(v) & 0xFFFFF800u) | col);
}

__global__ void __launch_bounds__(128) scores_mma_kernel() {
    extern __shared__ char smem[];
    uint32_t sb = smem_u32(smem);
    int tid = threadIdx.x;
    int w = tid >> 5, lane = tid & 31;
    int bh = blockIdx.x;
    int qt = blockIdx.y;

    const __half* qh_g = g_Qh + (size_t)(bh*S + qt*128)*DK;
    const __half* kh_g = g_Kh + (size_t)bh*S*DK;

    copy_tile128(sb + SQ, qh_g, tid);
    copy_tile128(sb + SKB + 0*SK_ST, kh_g, tid);
    CP_COMMIT();
    copy_tile128(sb + SKB + 1*SK_ST, kh_g + 128*DK, tid);
    CP_COMMIT();

    CP_WAIT1();
    __syncthreads();

    uint32_t aF[2][4][4];
    {
        int row16 = lane & 15;
        int half = lane >> 4;
        #pragma unroll
        for (int rb = 0; rb < 2; rb++) {
            uint32_t rowoff = (uint32_t)(w*32 + rb*16 + row16) * 128;
            #pragma unroll
            for (int ks = 0; ks < 4; ks++) {
                uint32_t unit = (uint32_t)(ks*2 + half);
                uint32_t off = rowoff + ((unit ^ (row16 & 7)) << 4);
                ldsm_x4(aF[rb][ks][0], aF[rb][ks][1], aF[rb][ks][2], aF[rb][ks][3], sb + SQ + off);
            }
        }
    }

    float m1[4] = {-1e30f,-1e30f,-1e30f,-1e30f};
    int bi = lane >> 3;
    int br = lane & 7;

    #pragma unroll 1
    for (int kt = 0; kt < 16; kt++) {
        if (kt > 0) {
            CP_WAIT1();
            __syncthreads();
        }
        uint32_t kb = sb + SKB + (kt & 1)*SK_ST;

        #pragma unroll
        for (int t = 0; t < 16; t++) {
            int row = t*8 + br;
            uint32_t rowoff = (uint32_t)row * 128;
            uint32_t sw0 = ((uint32_t)(bi    ) ^ (row & 7)) << 4;
            uint32_t sw1 = ((uint32_t)(bi + 4) ^ (row & 7)) << 4;
            uint32_t b0,b1,b2,b3,b4,b5,b6,b7;
            ldsm_x4(b0,b1,b2,b3, kb + rowoff + sw0);
            ldsm_x4(b4,b5,b6,b7, kb + rowoff + sw1);
            uint32_t colb = (uint32_t)(kt*128 + t*8 + (lane & 3)*2);

            #pragma unroll
            for (int rb = 0; rb < 2; rb++) {
                float cA0=0.f,cA1=0.f,cA2=0.f,cA3=0.f;
                float cB0=0.f,cB1=0.f,cB2=0.f,cB3=0.f;
                mma_f16(cA0,cA1,cA2,cA3, aF[rb][0][0],aF[rb][0][1],aF[rb][0][2],aF[rb][0][3], b0,b1);
                mma_f16(cB0,cB1,cB2,cB3, aF[rb][2][0],aF[rb][2][1],aF[rb][2][2],aF[rb][2][3], b4,b5);
                mma_f16(cA0,cA1,cA2,cA3, aF[rb][1][0],aF[rb][1][1],aF[rb][1][2],aF[rb][1][3], b2,b3);
                mma_f16(cB0,cB1,cB2,cB3, aF[rb][3][0],aF[rb][3][1],aF[rb][3][2],aF[rb][3][3], b6,b7);
                float v0 = cA0 + cB0, v1 = cA1 + cB1, v2 = cA2 + cB2, v3 = cA3 + cB3;
                int sA = rb*2 + 0, sB = rb*2 + 1;
                m1[sA] = fmaxf(m1[sA], fmaxf(packv(v0, colb), packv(v1, colb + 1)));
                m1[sB] = fmaxf(m1[sB], fmaxf(packv(v2, colb), packv(v3, colb + 1)));
            }
        }
        __syncthreads();
        if (kt + 2 < 16) {
            copy_tile128(sb + SKB + (kt & 1)*SK_ST, kh_g + (size_t)(kt+2)*128*DK, tid);
        }
        CP_COMMIT();
    }

    #pragma unroll
    for (int s = 0; s < 4; s++) {
        float a1 = m1[s];
        #pragma unroll
        for (int off = 1; off < 4; off <<= 1)
            a1 = fmaxf(a1, __shfl_xor_sync(0xFFFFFFFFu, a1, off));
        if ((lane & 3) == 0) {
            int rb = s >> 1, half = s & 1;
            int r = qt*128 + w*32 + rb*16 + half*8 + (lane >> 2);
            g_sidx[bh*S + r] = (int)(__float_as_uint(a1) & 0x7FFu);
        }
    }
}

// ---------------- fused xsum-final + analytic sumK (= xsum . wk^T + S*bk) ----------------
__global__ void __launch_bounds__(512) xsum_sumk_kernel(const float* __restrict__ wk,
                                                        const float* __restrict__ bk) {
    __shared__ float xs[D];
    int b = blockIdx.x, tid = threadIdx.x;
    int lane = tid & 31, w = tid >> 5;
    {
        float acc = 0.f;
        #pragma unroll 8
        for (int sc = 0; sc < 32; sc++) acc += g_xpart[(size_t)(b*32+sc)*D + tid];
        xs[tid] = acc;
        g_xsum[b*D + tid] = acc;
    }
    __syncthreads();
    #pragma unroll 1
    for (int oo = 0; oo < 32; oo++) {
        int o = w*32 + oo;
        const float* wr = wk + (size_t)o*D + lane;
        float acc = 0.f;
        #pragma unroll
        for (int k = 0; k < 16; k++) acc += xs[lane + k*32] * wr[k*32];
        #pragma unroll
        for (int off = 16; off > 0; off >>= 1) acc += __shfl_xor_sync(0xFFFFFFFFu, acc, off);
        if (lane == 0) {
            int h = o >> 6, d = o & 63;
            g_sumK[(b*H + h)*DK + d] = acc + (float)S * bk[o];
        }
    }
}

// ---------------- fixup: exact mean + exact dot at argmax -> sparsity ----------------
__global__ void __launch_bounds__(256) fixup_kernel() {
    int w = threadIdx.x >> 5, lane = threadIdx.x & 31;
    int g = blockIdx.x*8 + w;
    int bh = g >> 11;
    float q0 = g_Q[(size_t)g*DK + 2*lane];
    float q1 = g_Q[(size_t)g*DK + 2*lane + 1];
    float md = q0*g_sumK[bh*DK + 2*lane] + q1*g_sumK[bh*DK + 2*lane + 1];
    int idx = g_sidx[g];
    const float* kr = g_K + ((size_t)bh*S + idx)*DK;
    float e = q0*kr[2*lane] + q1*kr[2*lane + 1];
    #pragma unroll
    for (int off = 16; off > 0; off >>= 1) {
        md += __shfl_xor_sync(0xFFFFFFFFu, md, off);
        e  += __shfl_xor_sync(0xFFFFFFFFu, e,  off);
    }
    if (lane == 0) {
        float inv_log = 1.0f / logf((float)S);
        g_spars[g] = md * (1.0f/(8.0f*(float)S)) - e * 0.125f * inv_log;
    }
}

// ---------------- iterative top-53 per (b,h) ----------------
__global__ void topk_kernel() {
    __shared__ float vals[S];
    __shared__ float wm[8];
    __shared__ int   wi[8];
    int bh = blockIdx.x, tid = threadIdx.x;
    int lane = tid & 31, wid = tid >> 5;
    for (int i = tid; i < S; i += 256) vals[i] = g_spars[bh*S + i];
    __syncthreads();
    for (int it = 0; it < U; it++) {
        float best = -1e30f; int bidx = S;
        #pragma unroll
        for (int k = 0; k < 8; k++) {
            int i = tid + k*256;
            float v = vals[i];
            if (v > best || (v == best && i < bidx)) { best = v; bidx = i; }
        }
        #pragma unroll
        for (int off = 16; off > 0; off >>= 1) {
            float v2 = __shfl_down_sync(0xFFFFFFFFu, best, off);
            int i2 = __shfl_down_sync(0xFFFFFFFFu, bidx, off);
            if (v2 > best || (v2 == best && i2 < bidx)) { best = v2; bidx = i2; }
        }
        if (lane == 0) { wm[wid] = best; wi[wid] = bidx; }
        __syncthreads();
        if (tid == 0) {
            float m = wm[0]; int mi = wi[0];
            #pragma unroll
            for (int t = 1; t < 8; t++)
                if (wm[t] > m || (wm[t] == m && wi[t] < mi)) { m = wm[t]; mi = wi[t]; }
            g_topidx[bh*U + it] = mi;
            vals[mi] = -1e30f;
        }
        __syncthreads();
    }
}

// ---------------- fused meanV + ybase ----------------
__global__ void __launch_bounds__(512) meanv_ybase_kernel(
        const float* __restrict__ wv, const float* __restrict__ bv,
        const float* __restrict__ wo, const float* __restrict__ bo) {
    __shared__ float xs[D];
    __shared__ float mv[D];
    int b = blockIdx.x, tid = threadIdx.x;
    int lane = tid & 31, w = tid >> 5;
    xs[tid] = g_xsum[b*D + tid];
    __syncthreads();
    #pragma unroll 1
    for (int oo = 0; oo < 32; oo++) {
        int o = w*32 + oo;
        const float* wr = wv + (size_t)o*D + lane;
        float acc = 0.f;
        #pragma unroll
        for (int k = 0; k < 16; k++) acc += xs[lane + k*32] * wr[k*32];
        #pragma unroll
        for (int off = 16; off > 0; off >>= 1) acc += __shfl_xor_sync(0xFFFFFFFFu, acc, off);
        if (lane == 0) {
            float m = acc * (1.0f/(float)S) + bv[o];
            mv[o] = m;
            g_meanV[b*D + o] = m;
        }
    }
    __syncthreads();
    #pragma unroll 1
    for (int oo = 0; oo < 32; oo++) {
        int o = w*32 + oo;
        const float* wr = wo + (size_t)o*D + lane;
        float acc = 0.f;
        #pragma unroll
        for (int k = 0; k < 16; k++) acc += mv[lane + k*32] * wr[k*32];
        #pragma unroll
        for (int off = 16; off > 0; off >>= 1) acc += __shfl_xor_sync(0xFFFFFFFFu, acc, off);
        if (lane == 0) g_ybase[b*D + o] = acc + bo[o];
    }
}

// ---------------- corrections: one block per (b,h) ----------------
__global__ void __launch_bounds__(256) corr_kernel(const float* __restrict__ x,
                                                   const float* __restrict__ wv,
                                                   const float* __restrict__ bv) {
    __shared__ float sbuf[64*65 + 56*65];
    __shared__ int   s_idx[56];
    __shared__ float s_v[56];
    int bh = blockIdx.x;
    int b = bh / H, h = bh % H;
    int tid = threadIdx.x;
    if (tid < U) s_idx[tid] = g_topidx[bh*U + tid];
    __syncthreads();

    float* sq = sbuf;
    float* sk = sbuf + U*DK;
    for (int e = tid; e < U*DK; e += 256) sq[e] = g_Q[(size_t)bh*S*DK + e];
    for (int e = tid; e < U*DK; e += 256) {
        int i = e >> 6, d = e & 63;
        sk[e] = g_K[((size_t)bh*S + s_idx[i])*DK + d];
    }
    __syncthreads();
    if (tid < U) {
        float acc = 0.f;
        #pragma unroll 8
        for (int d = 0; d < DK; d++) acc += sq[tid*DK + d] * sk[tid*DK + d];
        s_v[tid] = acc * 0.125f;
    }
    __syncthreads();

    float* wvs = sbuf;
    float* xjs = sbuf + 64*65;
    int ci = tid & 15, ri = tid >> 4;
    float acc[4][4] = {};
    for (int dt = 0; dt < 8; dt++) {
        __syncthreads();
        for (int e = tid; e < 64*64; e += 256) {
            int r = e >> 6, c2 = e & 63;
            wvs[r*65 + c2] = wv[((size_t)(h*64 + r))*D + dt*64 + c2];
        }
        for (int e = tid; e < 56*64; e += 256) {
            int i = e >> 6, c2 = e & 63;
            xjs[i*65 + c2] = (i < U) ? x[((size_t)b*S + s_idx[i])*D + dt*64 + c2] : 0.f;
        }
        __syncthreads();
        if (ri < 14) {
            #pragma unroll 4
            for (int dd = 0; dd < 64; dd++) {
                float xv0 = xjs[(ri*4+0)*65 + dd];
                float xv1 = xjs[(ri*4+1)*65 + dd];
                float xv2 = xjs[(ri*4+2)*65 + dd];
                float xv3 = xjs[(ri*4+3)*65 + dd];
                float w0 = wvs[(ci*4+0)*65 + dd];
                float w1 = wvs[(ci*4+1)*65 + dd];
                float w2 = wvs[(ci*4+2)*65 + dd];
                float w3 = wvs[(ci*4+3)*65 + dd];
                acc[0][0] += xv0*w0; acc[0][1] += xv0*w1; acc[0][2] += xv0*w2; acc[0][3] += xv0*w3;
                acc[1][0] += xv1*w0; acc[1][1] += xv1*w1; acc[1][2] += xv1*w2; acc[1][3] += xv1*w3;
                acc[2][0] += xv2*w0; acc[2][1] += xv2*w1; acc[2][2] += xv2*w2; acc[2][3] += xv2*w3;
                acc[3][0] += xv3*w0; acc[3][1] += xv3*w1; acc[3][2] += xv3*w2; acc[3][3] += xv3*w3;
            }
        }
    }

    if (ri < 14) {
        #pragma unroll
        for (int r = 0; r < 4; r++) {
            int i = ri*4 + r;
            if (i >= U) continue;
            float ev = expf(s_v[i]);
            float em1 = ev - 1.0f;
            float Z = ev + (float)(S - 1);
            #pragma unroll
            for (int c2 = 0; c2 < 4; c2++) {
                int col = ci*4 + c2;
                float Vj = acc[r][c2] + bv[h*64 + col];
                float mvv = g_meanV[b*D + h*64 + col];
                g_outcat[((size_t)(b*U + i))*D + h*64 + col] = ((float)S * mvv + em1 * Vj) / Z;
            }
        }
    }
}

// ---------------- out-projection for the 212 corrected rows ----------------
__global__ void outproj_kernel(const float* __restrict__ wo, const float* __restrict__ bo,
                               float* __restrict__ y) {
    __shared__ float As[32][68];
    __shared__ float Bs[32][68];
    int tid = threadIdx.x;
    int tx = tid & 15, ty = tid >> 4;
    int m0 = blockIdx.x * 64;
    int n0 = blockIdx.y * 64;
    float acc[4][4] = {};
    for (int d0 = 0; d0 < D; d0 += 32) {
        #pragma unroll
        for (int i = 0; i < 2; i++) {
            int e = tid + i*256;
            int row = e >> 3;
            int c4 = e & 7;
            float4 v = make_float4(0.f, 0.f, 0.f, 0.f);
            if (m0 + row < B*U)
                v = *(const float4*)(g_outcat + (size_t)(m0+row)*D + d0 + c4*4);
            As[c4*4+0][row] = v.x; As[c4*4+1][row] = v.y;
            As[c4*4+2][row] = v.z; As[c4*4+3][row] = v.w;
            float4 u = *(const float4*)(wo + (size_t)(n0+row)*D + d0 + c4*4);
            Bs[c4*4+0][row] = u.x; Bs[c4*4+1][row] = u.y;
            Bs[c4*4+2][row] = u.z; Bs[c4*4+3][row] = u.w;
        }
        __syncthreads();
        #pragma unroll
        for (int kk = 0; kk < 32; kk++) {
            float4 a = *(const float4*)&As[kk][tx*4];
            float4 bv4 = *(const float4*)&Bs[kk][ty*4];
            float av[4] = {a.x, a.y, a.z, a.w};
            float bw[4] = {bv4.x, bv4.y, bv4.z, bv4.w};
            #pragma unroll
            for (int i = 0; i < 4; i++)
                #pragma unroll
                for (int j = 0; j < 4; j++)
                    acc[i][j] += av[i] * bw[j];
        }
        __syncthreads();
    }
    #pragma unroll
    for (int i = 0; i < 4; i++) {
        int m = m0 + tx*4 + i;
        if (m < B*U) {
            int b = m / U, s = m % U;
            float* op = y + ((size_t)b*S + s)*D + n0 + ty*4;
            #pragma unroll
            for (int j = 0; j < 4; j++)
                op[j] = acc[i][j] + bo[n0 + ty*4 + j];
        }
    }
}

// ---------------- broadcast the uniform rows (s >= U) ----------------
__global__ void bcast_kernel(float* __restrict__ y) {
    int id = blockIdx.x * blockDim.x + threadIdx.x;
    const int per_b = (S - U) * (D/4);
    const int total = B * per_b;
    if (id >= total) return;
    int b = id / per_b;
    int r = id % per_b;
    int s = U + r / (D/4);
    int d4 = r % (D/4);
    float4 v = *(const float4*)(g_ybase + b*D + d4*4);
    *(float4*)(y + ((size_t)b*S + s)*D + d4*4) = v;
}

extern "C" void kernel_launch(void* const* d_in, const int* in_sizes, int n_in,
                              void* d_out, int out_size) {
    const float* x  = (const float*)d_in[0];
    const float* wq = (const float*)d_in[1];
    const float* bq = (const float*)d_in[2];
    const float* wk = (const float*)d_in[3];
    const float* bk = (const float*)d_in[4];
    const float* wv = (const float*)d_in[5];
    const float* bv = (const float*)d_in[6];
    const float* wo = (const float*)d_in[7];
    const float* bo = (const float*)d_in[8];
    float* y = (float*)d_out;

    cudaFuncSetAttribute(scores_mma_kernel, cudaFuncAttributeMaxDynamicSharedMemorySize, SM2_TOTAL);
    cudaFuncSetAttribute(proj_mma_kernel, cudaFuncAttributeMaxDynamicSharedMemorySize, PJ_SM_TOTAL);

    {
        const int total = XU + 2*WU;
        convert_xw_kernel<<<(total + 255)/256, 256>>>(x, wq, wk);          // u1
    }

    dim3 pg(B*S/128, D/64, 2);
    proj_mma_kernel<<<pg, 256, PJ_SM_TOTAL>>>(bq, bk);                     // u2

    sumx_part_kernel<<<B*32, 512>>>(x);                                    // u3

    dim3 sg(BH, 16);
    scores_mma_kernel<<<sg, 128, SM2_TOTAL>>>();                           // u4 <- ncu

    xsum_sumk_kernel<<<B, 512>>>(wk, bk);                                  // u5

    fixup_kernel<<<BH*S/8, 256>>>();                                       // u6

    topk_kernel<<<BH, 256>>>();                                            // u7

    meanv_ybase_kernel<<<B, 512>>>(wv, bv, wo, bo);                        // u8

    corr_kernel<<<BH, 256>>>(x, wv, bv);                                   // u9

    dim3 og((B*U + 63)/64, D/64);
    outproj_kernel<<<og, 256>>>(wo, bo, y);                                // u10

    const int per_b = (S - U) * (D/4);
    bcast_kernel<<<(B*per_b + 255)/256, 256>>>(y);                         // u11
}

// round 16
// speedup vs baseline: 1.2596x; 1.0417x over previous
#include <cuda_runtime.h>
#include <cuda_fp16.h>
#include <math.h>
#include <stdint.h>

#define B 4
#define S 2048
#define D 512
#define H 8
#define DK 64
#define U 53
#define BH (B*H)

// ---------------- scratch ----------------
__device__ float g_Q[B*H*S*DK];       // fp32 [bh][s][k]
__device__ float g_K[B*H*S*DK];
__device__ float g_spars[B*H*S];
__device__ int   g_topidx[B*H*U];
__device__ float g_xpart[32*B*D];
__device__ float g_xsum[B*D];
__device__ float g_meanV[B*D];
__device__ float g_ybase[B*D];
__device__ float g_outcat[B*U*D];
__device__ float g_sumK[BH*DK];
__device__ int   g_sidx[BH*S];
// fp16 operands
__device__ __half g_Qh[BH*S*DK];
__device__ __half g_Kh[BH*S*DK];
__device__ __half g_xh[B*S*D];
__device__ __half g_wqh[D*D];
__device__ __half g_wkh[D*D];

// ================= warp-mma helpers =================
__device__ __forceinline__ uint32_t smem_u32(const void* p) {
    uint32_t a;
    asm("{ .reg .u64 t; cvta.to.shared.u64 t, %1; cvt.u32.u64 %0, t; }" : "=r"(a) : "l"(p));
    return a;
}
__device__ __forceinline__ void ldsm_x4(uint32_t& r0, uint32_t& r1, uint32_t& r2, uint32_t& r3, uint32_t addr) {
    asm volatile("ldmatrix.sync.aligned.m8n8.x4.shared.b16 {%0,%1,%2,%3}, [%4];"
        : "=r"(r0), "=r"(r1), "=r"(r2), "=r"(r3) : "r"(addr));
}
__device__ __forceinline__ void mma_f16(float& c0, float& c1, float& c2, float& c3,
                                        uint32_t a0, uint32_t a1, uint32_t a2, uint32_t a3,
                                        uint32_t b0, uint32_t b1) {
    asm volatile("mma.sync.aligned.m16n8k16.row.col.f32.f16.f16.f32 "
        "{%0,%1,%2,%3}, {%4,%5,%6,%7}, {%8,%9}, {%0,%1,%2,%3};"
        : "+f"(c0), "+f"(c1), "+f"(c2), "+f"(c3)
        : "r"(a0), "r"(a1), "r"(a2), "r"(a3), "r"(b0), "r"(b1));
}
#define CP_ASYNC16(dst, src) \
    asm volatile("cp.async.cg.shared.global [%0], [%1], 16;" :: "r"(dst), "l"(src))
#define CP_COMMIT() asm volatile("cp.async.commit_group;" ::: "memory")
#define CP_WAIT1()  asm volatile("cp.async.wait_group 1;" ::: "memory")

// ---------------- column sums of x (partials) ----------------
__global__ void sumx_part_kernel(const float* __restrict__ x) {
    int blk = blockIdx.x;
    int b = blk >> 5, sc = blk & 31;
    int d = threadIdx.x;
    const float* p = x + ((size_t)b*S + sc*64)*D + d;
    float acc = 0.f;
    #pragma unroll 8
    for (int s = 0; s < 64; s++) acc += p[(size_t)s*D];
    g_xpart[(size_t)blk*D + d] = acc;
}

// ---------------- fp32 -> fp16 for x, wq, wk ----------------
#define XU (B*S*D/8)
#define WU (D*D/8)
__global__ void convert_xw_kernel(const float* __restrict__ x, const float* __restrict__ wq,
                                  const float* __restrict__ wk) {
    int id = blockIdx.x * blockDim.x + threadIdx.x;
    if (id >= XU + 2*WU) return;
    const float* src;
    __half* dh;
    int u;
    if (id < XU)                { u = id;            src = x  + (size_t)u*8; dh = g_xh;  }
    else if (id < XU + WU)      { u = id - XU;       src = wq + (size_t)u*8; dh = g_wqh; }
    else                        { u = id - XU - WU;  src = wk + (size_t)u*8; dh = g_wkh; }
    float4 a = *(const float4*)src;
    float4 b4 = *(const float4*)(src + 4);
    float vs[8] = {a.x, a.y, a.z, a.w, b4.x, b4.y, b4.z, b4.w};
    union { __half h[8]; int4 v; } hv;
    #pragma unroll
    for (int i = 0; i < 8; i++) hv.h[i] = __float2half_rn(vs[i]);
    ((int4*)dh)[u] = hv.v;
}

// ---------------- Q/K projection via warp-mma (fp16), z = which ----------------
#define PJ_STAGE 24576          // x 16KB | w 8KB
#define PJ_XH 0
#define PJ_WH 16384
#define PJ_SM_TOTAL (2*PJ_STAGE)  // 48 KB

__device__ __forceinline__ void pj_copy_x(uint32_t sdst, const __half* g0, int tid) {
    #pragma unroll
    for (int i = 0; i < 4; i++) {
        int u = tid + i*256;
        int row = u >> 3, cu = u & 7;
        uint32_t dst = sdst + row*128 + ((cu ^ (row & 7)) << 4);
        CP_ASYNC16(dst, (const char*)g0 + (size_t)row*1024 + cu*16);
    }
}
__device__ __forceinline__ void pj_copy_w(uint32_t sdst, const __half* g0, int tid) {
    #pragma unroll
    for (int i = 0; i < 2; i++) {
        int u = tid + i*256;
        int row = u >> 3, cu = u & 7;
        uint32_t dst = sdst + row*128 + ((cu ^ (row & 7)) << 4);
        CP_ASYNC16(dst, (const char*)g0 + (size_t)row*1024 + cu*16);
    }
}

__global__ void __launch_bounds__(256) proj_mma_kernel(const float* __restrict__ bq,
                                                       const float* __restrict__ bk) {
    extern __shared__ char smem[];
    uint32_t sb = smem_u32(smem);
    int tid = threadIdx.x;
    int w = tid >> 5, lane = tid & 31;
    int m0 = blockIdx.x * 128;
    int n0 = blockIdx.y * 64;
    int which = blockIdx.z;
    const float* bias = which ? bk : bq;

    const __half* xh = g_xh + (size_t)m0*D;
    const __half* wh = (which ? g_wkh : g_wqh) + (size_t)n0*D;
    float* outf = which ? g_K : g_Q;
    __half* outh = which ? g_Kh : g_Qh;

    pj_copy_x(sb + 0*PJ_STAGE + PJ_XH, xh, tid);
    pj_copy_w(sb + 0*PJ_STAGE + PJ_WH, wh, tid);
    CP_COMMIT();
    pj_copy_x(sb + 1*PJ_STAGE + PJ_XH, xh + 64, tid);
    pj_copy_w(sb + 1*PJ_STAGE + PJ_WH, wh + 64, tid);
    CP_COMMIT();

    float c[8][4];
    #pragma unroll
    for (int j = 0; j < 8; j++)
        #pragma unroll
        for (int r = 0; r < 4; r++) c[j][r] = 0.f;

    int row16 = lane & 15;
    int half = lane >> 4;
    int bi = lane >> 3;
    int br = lane & 7;

    #pragma unroll 1
    for (int kt = 0; kt < 8; kt++) {
        CP_WAIT1();
        __syncthreads();
        uint32_t st = sb + (kt & 1)*PJ_STAGE;

        uint32_t aF[4][4];
        {
            uint32_t rowoff = (uint32_t)(w*16 + row16) * 128;
            #pragma unroll
            for (int ks = 0; ks < 4; ks++) {
                uint32_t unit = (uint32_t)(ks*2 + half);
                uint32_t off = rowoff + ((unit ^ (row16 & 7)) << 4);
                ldsm_x4(aF[ks][0], aF[ks][1], aF[ks][2], aF[ks][3], st + PJ_XH + off);
            }
        }

        #pragma unroll
        for (int j = 0; j < 8; j++) {
            int row = j*8 + br;
            uint32_t rowoff = (uint32_t)row * 128;
            uint32_t sw0 = ((uint32_t)(bi    ) ^ (row & 7)) << 4;
            uint32_t sw1 = ((uint32_t)(bi + 4) ^ (row & 7)) << 4;
            uint32_t b0,b1,b2,b3,b4,b5,b6,b7;
            ldsm_x4(b0,b1,b2,b3, st + PJ_WH + rowoff + sw0);
            ldsm_x4(b4,b5,b6,b7, st + PJ_WH + rowoff + sw1);

            mma_f16(c[j][0],c[j][1],c[j][2],c[j][3], aF[0][0],aF[0][1],aF[0][2],aF[0][3], b0,b1);
            mma_f16(c[j][0],c[j][1],c[j][2],c[j][3], aF[1][0],aF[1][1],aF[1][2],aF[1][3], b2,b3);
            mma_f16(c[j][0],c[j][1],c[j][2],c[j][3], aF[2][0],aF[2][1],aF[2][2],aF[2][3], b4,b5);
            mma_f16(c[j][0],c[j][1],c[j][2],c[j][3], aF[3][0],aF[3][1],aF[3][2],aF[3][3], b6,b7);
        }
        __syncthreads();
        if (kt + 2 < 8) {
            uint32_t st2 = sb + (kt & 1)*PJ_STAGE;
            int koff = (kt + 2) * 64;
            pj_copy_x(st2 + PJ_XH, xh + koff, tid);
            pj_copy_w(st2 + PJ_WH, wh + koff, tid);
        }
        CP_COMMIT();
    }

    int r0 = m0 + w*16 + (lane >> 2);
    #pragma unroll
    for (int j = 0; j < 8; j++) {
        int n = n0 + j*8 + (lane & 3)*2;
        int h = n >> 6, k = n & 63;
        float b0 = bias[n], b1 = bias[n+1];
        #pragma unroll
        for (int rr = 0; rr < 2; rr++) {
            int m = r0 + rr*8;
            int b_ = m >> 11, s = m & (S-1);
            size_t idx = (((size_t)(b_*H + h)*S + s)*DK) + k;
            float v0 = c[j][rr*2+0] + b0;
            float v1 = c[j][rr*2+1] + b1;
            *(float2*)(outf + idx) = make_float2(v0, v1);
            union { __half h2[2]; uint32_t u; } ph;
            ph.h2[0] = __float2half_rn(v0);
            ph.h2[1] = __float2half_rn(v1);
            *(uint32_t*)(outh + idx) = ph.u;
        }
    }
}

// ---------------- scores: fp16 QK^T, m64/warp, packed (value|index) max ----------------
// CTA = 256 q-rows; 4 warps x m64 (4 row-blocks of 16). Each K fragment feeds 16 MMAs.
#define SQ 0
#define SKB 32768
#define SK_ST 16384
#define SM2_TOTAL (SKB + 2*SK_ST)   // 64 KB

__device__ __forceinline__ void copy_qtile256(uint32_t sdst, const __half* gsrc, int tid) {
    #pragma unroll
    for (int i = 0; i < 16; i++) {
        int u = tid + i*128;              // 2048 units (256 rows x 8)
        int row = u >> 3, cu = u & 7;
        uint32_t dst = sdst + row*128 + ((cu ^ (row & 7)) << 4);
        CP_ASYNC16(dst, (const char*)gsrc + (size_t)u*16);
    }
}
__device__ __forceinline__ void copy_tile128(uint32_t sdst, const __half* gsrc, int tid) {
    #pragma unroll
    for (int i = 0; i < 8; i++) {
        int u = tid + i*128;              // 1024 units (128 rows x 8)
        int row = u >> 3, cu = u & 7;
        uint32_t dst = sdst + row*128 + ((cu ^ (row & 7)) << 4);
        CP_ASYNC16(dst, (const char*)gsrc + (size_t)u*16);
    }
}

__device__ __forceinline__ float packv(float v, uint32_t col) {
    return __uint_as_float((__float_as_uint(v) & 0xFFFFF800u) | col);
}

__global__ void __launch_bounds__(128) scores_mma_kernel() {
    extern __shared__ char smem[];
    uint32_t sb = smem_u32(smem);
    int tid = threadIdx.x;
    int w = tid >> 5, lane = tid & 31;
    int bh = blockIdx.x;
    int qt = blockIdx.y;                  // 8 tiles of 256 q-rows

    const __half* qh_g = g_Qh + (size_t)(bh*S + qt*256)*DK;
    const __half* kh_g = g_Kh + (size_t)bh*S*DK;

    copy_qtile256(sb + SQ, qh_g, tid);
    copy_tile128(sb + SKB + 0*SK_ST, kh_g, tid);
    CP_COMMIT();
    copy_tile128(sb + SKB + 1*SK_ST, kh_g + 128*DK, tid);
    CP_COMMIT();

    CP_WAIT1();
    __syncthreads();

    uint32_t aF[4][4][4];                 // [row-block][k-step][reg]
    {
        int row16 = lane & 15;
        int half = lane >> 4;
        #pragma unroll
        for (int rb = 0; rb < 4; rb++) {
            uint32_t rowoff = (uint32_t)(w*64 + rb*16 + row16) * 128;
            #pragma unroll
            for (int ks = 0; ks < 4; ks++) {
                uint32_t unit = (uint32_t)(ks*2 + half);
                uint32_t off = rowoff + ((unit ^ (row16 & 7)) << 4);
                ldsm_x4(aF[rb][ks][0], aF[rb][ks][1], aF[rb][ks][2], aF[rb][ks][3], sb + SQ + off);
            }
        }
    }

    float m1[8];
    #pragma unroll
    for (int s = 0; s < 8; s++) m1[s] = -1e30f;
    int bi = lane >> 3;
    int br = lane & 7;

    #pragma unroll 1
    for (int kt = 0; kt < 16; kt++) {
        if (kt > 0) {
            CP_WAIT1();
            __syncthreads();
        }
        uint32_t kb = sb + SKB + (kt & 1)*SK_ST;

        #pragma unroll
        for (int t = 0; t < 16; t++) {
            int row = t*8 + br;
            uint32_t rowoff = (uint32_t)row * 128;
            uint32_t sw0 = ((uint32_t)(bi    ) ^ (row & 7)) << 4;
            uint32_t sw1 = ((uint32_t)(bi + 4) ^ (row & 7)) << 4;
            uint32_t b0,b1,b2,b3,b4,b5,b6,b7;
            ldsm_x4(b0,b1,b2,b3, kb + rowoff + sw0);
            ldsm_x4(b4,b5,b6,b7, kb + rowoff + sw1);
            uint32_t colb = (uint32_t)(kt*128 + t*8 + (lane & 3)*2);

            #pragma unroll
            for (int rb = 0; rb < 4; rb++) {
                float cA0=0.f,cA1=0.f,cA2=0.f,cA3=0.f;
                float cB0=0.f,cB1=0.f,cB2=0.f,cB3=0.f;
                mma_f16(cA0,cA1,cA2,cA3, aF[rb][0][0],aF[rb][0][1],aF[rb][0][2],aF[rb][0][3], b0,b1);
                mma_f16(cB0,cB1,cB2,cB3, aF[rb][2][0],aF[rb][2][1],aF[rb][2][2],aF[rb][2][3], b4,b5);
                mma_f16(cA0,cA1,cA2,cA3, aF[rb][1][0],aF[rb][1][1],aF[rb][1][2],aF[rb][1][3], b2,b3);
                mma_f16(cB0,cB1,cB2,cB3, aF[rb][3][0],aF[rb][3][1],aF[rb][3][2],aF[rb][3][3], b6,b7);
                float v0 = cA0 + cB0, v1 = cA1 + cB1, v2 = cA2 + cB2, v3 = cA3 + cB3;
                int sA = rb*2 + 0, sB = rb*2 + 1;
                m1[sA] = fmaxf(m1[sA], fmaxf(packv(v0, colb), packv(v1, colb + 1)));
                m1[sB] = fmaxf(m1[sB], fmaxf(packv(v2, colb), packv(v3, colb + 1)));
            }
        }
        __syncthreads();
        if (kt + 2 < 16) {
            copy_tile128(sb + SKB + (kt & 1)*SK_ST, kh_g + (size_t)(kt+2)*128*DK, tid);
        }
        CP_COMMIT();
    }

    #pragma unroll
    for (int s = 0; s < 8; s++) {
        float a1 = m1[s];
        #pragma unroll
        for (int off = 1; off < 4; off <<= 1)
            a1 = fmaxf(a1, __shfl_xor_sync(0xFFFFFFFFu, a1, off));
        if ((lane & 3) == 0) {
            int rb = s >> 1, half = s & 1;
            int r = qt*256 + w*64 + rb*16 + half*8 + (lane >> 2);
            g_sidx[bh*S + r] = (int)(__float_as_uint(a1) & 0x7FFu);
        }
    }
}

// ---------------- fused xsum-final + analytic sumK (= xsum . wk^T + S*bk) ----------------
__global__ void __launch_bounds__(512) xsum_sumk_kernel(const float* __restrict__ wk,
                                                        const float* __restrict__ bk) {
    __shared__ float xs[D];
    int b = blockIdx.x, tid = threadIdx.x;
    int lane = tid & 31, w = tid >> 5;
    {
        float acc = 0.f;
        #pragma unroll 8
        for (int sc = 0; sc < 32; sc++) acc += g_xpart[(size_t)(b*32+sc)*D + tid];
        xs[tid] = acc;
        g_xsum[b*D + tid] = acc;
    }
    __syncthreads();
    #pragma unroll 1
    for (int oo = 0; oo < 32; oo++) {
        int o = w*32 + oo;
        const float* wr = wk + (size_t)o*D + lane;
        float acc = 0.f;
        #pragma unroll
        for (int k = 0; k < 16; k++) acc += xs[lane + k*32] * wr[k*32];
        #pragma unroll
        for (int off = 16; off > 0; off >>= 1) acc += __shfl_xor_sync(0xFFFFFFFFu, acc, off);
        if (lane == 0) {
            int h = o >> 6, d = o & 63;
            g_sumK[(b*H + h)*DK + d] = acc + (float)S * bk[o];
        }
    }
}

// ---------------- fixup: exact mean + exact dot at argmax -> sparsity ----------------
__global__ void __launch_bounds__(256) fixup_kernel() {
    int w = threadIdx.x >> 5, lane = threadIdx.x & 31;
    int g = blockIdx.x*8 + w;
    int bh = g >> 11;
    float q0 = g_Q[(size_t)g*DK + 2*lane];
    float q1 = g_Q[(size_t)g*DK + 2*lane + 1];
    float md = q0*g_sumK[bh*DK + 2*lane] + q1*g_sumK[bh*DK + 2*lane + 1];
    int idx = g_sidx[g];
    const float* kr = g_K + ((size_t)bh*S + idx)*DK;
    float e = q0*kr[2*lane] + q1*kr[2*lane + 1];
    #pragma unroll
    for (int off = 16; off > 0; off >>= 1) {
        md += __shfl_xor_sync(0xFFFFFFFFu, md, off);
        e  += __shfl_xor_sync(0xFFFFFFFFu, e,  off);
    }
    if (lane == 0) {
        float inv_log = 1.0f / logf((float)S);
        g_spars[g] = md * (1.0f/(8.0f*(float)S)) - e * 0.125f * inv_log;
    }
}

// ---------------- iterative top-53 per (b,h) ----------------
__global__ void topk_kernel() {
    __shared__ float vals[S];
    __shared__ float wm[8];
    __shared__ int   wi[8];
    int bh = blockIdx.x, tid = threadIdx.x;
    int lane = tid & 31, wid = tid >> 5;
    for (int i = tid; i < S; i += 256) vals[i] = g_spars[bh*S + i];
    __syncthreads();
    for (int it = 0; it < U; it++) {
        float best = -1e30f; int bidx = S;
        #pragma unroll
        for (int k = 0; k < 8; k++) {
            int i = tid + k*256;
            float v = vals[i];
            if (v > best || (v == best && i < bidx)) { best = v; bidx = i; }
        }
        #pragma unroll
        for (int off = 16; off > 0; off >>= 1) {
            float v2 = __shfl_down_sync(0xFFFFFFFFu, best, off);
            int i2 = __shfl_down_sync(0xFFFFFFFFu, bidx, off);
            if (v2 > best || (v2 == best && i2 < bidx)) { best = v2; bidx = i2; }
        }
        if (lane == 0) { wm[wid] = best; wi[wid] = bidx; }
        __syncthreads();
        if (tid == 0) {
            float m = wm[0]; int mi = wi[0];
            #pragma unroll
            for (int t = 1; t < 8; t++)
                if (wm[t] > m || (wm[t] == m && wi[t] < mi)) { m = wm[t]; mi = wi[t]; }
            g_topidx[bh*U + it] = mi;
            vals[mi] = -1e30f;
        }
        __syncthreads();
    }
}

// ---------------- fused meanV + ybase ----------------
__global__ void __launch_bounds__(512) meanv_ybase_kernel(
        const float* __restrict__ wv, const float* __restrict__ bv,
        const float* __restrict__ wo, const float* __restrict__ bo) {
    __shared__ float xs[D];
    __shared__ float mv[D];
    int b = blockIdx.x, tid = threadIdx.x;
    int lane = tid & 31, w = tid >> 5;
    xs[tid] = g_xsum[b*D + tid];
    __syncthreads();
    #pragma unroll 1
    for (int oo = 0; oo < 32; oo++) {
        int o = w*32 + oo;
        const float* wr = wv + (size_t)o*D + lane;
        float acc = 0.f;
        #pragma unroll
        for (int k = 0; k < 16; k++) acc += xs[lane + k*32] * wr[k*32];
        #pragma unroll
        for (int off = 16; off > 0; off >>= 1) acc += __shfl_xor_sync(0xFFFFFFFFu, acc, off);
        if (lane == 0) {
            float m = acc * (1.0f/(float)S) + bv[o];
            mv[o] = m;
            g_meanV[b*D + o] = m;
        }
    }
    __syncthreads();
    #pragma unroll 1
    for (int oo = 0; oo < 32; oo++) {
        int o = w*32 + oo;
        const float* wr = wo + (size_t)o*D + lane;
        float acc = 0.f;
        #pragma unroll
        for (int k = 0; k < 16; k++) acc += mv[lane + k*32] * wr[k*32];
        #pragma unroll
        for (int off = 16; off > 0; off >>= 1) acc += __shfl_xor_sync(0xFFFFFFFFu, acc, off);
        if (lane == 0) g_ybase[b*D + o] = acc + bo[o];
    }
}

// ---------------- corrections: one block per (b,h) ----------------
__global__ void __launch_bounds__(256) corr_kernel(const float* __restrict__ x,
                                                   const float* __restrict__ wv,
                                                   const float* __restrict__ bv) {
    __shared__ float sbuf[64*65 + 56*65];
    __shared__ int   s_idx[56];
    __shared__ float s_v[56];
    int bh = blockIdx.x;
    int b = bh / H, h = bh % H;
    int tid = threadIdx.x;
    if (tid < U) s_idx[tid] = g_topidx[bh*U + tid];
    __syncthreads();

    float* sq = sbuf;
    float* sk = sbuf + U*DK;
    for (int e = tid; e < U*DK; e += 256) sq[e] = g_Q[(size_t)bh*S*DK + e];
    for (int e = tid; e < U*DK; e += 256) {
        int i = e >> 6, d = e & 63;
        sk[e] = g_K[((size_t)bh*S + s_idx[i])*DK + d];
    }
    __syncthreads();
    if (tid < U) {
        float acc = 0.f;
        #pragma unroll 8
        for (int d = 0; d < DK; d++) acc += sq[tid*DK + d] * sk[tid*DK + d];
        s_v[tid] = acc * 0.125f;
    }
    __syncthreads();

    float* wvs = sbuf;
    float* xjs = sbuf + 64*65;
    int ci = tid & 15, ri = tid >> 4;
    float acc[4][4] = {};
    for (int dt = 0; dt < 8; dt++) {
        __syncthreads();
        for (int e = tid; e < 64*64; e += 256) {
            int r = e >> 6, c2 = e & 63;
            wvs[r*65 + c2] = wv[((size_t)(h*64 + r))*D + dt*64 + c2];
        }
        for (int e = tid; e < 56*64; e += 256) {
            int i = e >> 6, c2 = e & 63;
            xjs[i*65 + c2] = (i < U) ? x[((size_t)b*S + s_idx[i])*D + dt*64 + c2] : 0.f;
        }
        __syncthreads();
        if (ri < 14) {
            #pragma unroll 4
            for (int dd = 0; dd < 64; dd++) {
                float xv0 = xjs[(ri*4+0)*65 + dd];
                float xv1 = xjs[(ri*4+1)*65 + dd];
                float xv2 = xjs[(ri*4+2)*65 + dd];
                float xv3 = xjs[(ri*4+3)*65 + dd];
                float w0 = wvs[(ci*4+0)*65 + dd];
                float w1 = wvs[(ci*4+1)*65 + dd];
                float w2 = wvs[(ci*4+2)*65 + dd];
                float w3 = wvs[(ci*4+3)*65 + dd];
                acc[0][0] += xv0*w0; acc[0][1] += xv0*w1; acc[0][2] += xv0*w2; acc[0][3] += xv0*w3;
                acc[1][0] += xv1*w0; acc[1][1] += xv1*w1; acc[1][2] += xv1*w2; acc[1][3] += xv1*w3;
                acc[2][0] += xv2*w0; acc[2][1] += xv2*w1; acc[2][2] += xv2*w2; acc[2][3] += xv2*w3;
                acc[3][0] += xv3*w0; acc[3][1] += xv3*w1; acc[3][2] += xv3*w2; acc[3][3] += xv3*w3;
            }
        }
    }

    if (ri < 14) {
        #pragma unroll
        for (int r = 0; r < 4; r++) {
            int i = ri*4 + r;
            if (i >= U) continue;
            float ev = expf(s_v[i]);
            float em1 = ev - 1.0f;
            float Z = ev + (float)(S - 1);
            #pragma unroll
            for (int c2 = 0; c2 < 4; c2++) {
                int col = ci*4 + c2;
                float Vj = acc[r][c2] + bv[h*64 + col];
                float mvv = g_meanV[b*D + h*64 + col];
                g_outcat[((size_t)(b*U + i))*D + h*64 + col] = ((float)S * mvv + em1 * Vj) / Z;
            }
        }
    }
}

// ---------------- out-projection for the 212 corrected rows ----------------
__global__ void outproj_kernel(const float* __restrict__ wo, const float* __restrict__ bo,
                               float* __restrict__ y) {
    __shared__ float As[32][68];
    __shared__ float Bs[32][68];
    int tid = threadIdx.x;
    int tx = tid & 15, ty = tid >> 4;
    int m0 = blockIdx.x * 64;
    int n0 = blockIdx.y * 64;
    float acc[4][4] = {};
    for (int d0 = 0; d0 < D; d0 += 32) {
        #pragma unroll
        for (int i = 0; i < 2; i++) {
            int e = tid + i*256;
            int row = e >> 3;
            int c4 = e & 7;
            float4 v = make_float4(0.f, 0.f, 0.f, 0.f);
            if (m0 + row < B*U)
                v = *(const float4*)(g_outcat + (size_t)(m0+row)*D + d0 + c4*4);
            As[c4*4+0][row] = v.x; As[c4*4+1][row] = v.y;
            As[c4*4+2][row] = v.z; As[c4*4+3][row] = v.w;
            float4 u = *(const float4*)(wo + (size_t)(n0+row)*D + d0 + c4*4);
            Bs[c4*4+0][row] = u.x; Bs[c4*4+1][row] = u.y;
            Bs[c4*4+2][row] = u.z; Bs[c4*4+3][row] = u.w;
        }
        __syncthreads();
        #pragma unroll
        for (int kk = 0; kk < 32; kk++) {
            float4 a = *(const float4*)&As[kk][tx*4];
            float4 bv4 = *(const float4*)&Bs[kk][ty*4];
            float av[4] = {a.x, a.y, a.z, a.w};
            float bw[4] = {bv4.x, bv4.y, bv4.z, bv4.w};
            #pragma unroll
            for (int i = 0; i < 4; i++)
                #pragma unroll
                for (int j = 0; j < 4; j++)
                    acc[i][j] += av[i] * bw[j];
        }
        __syncthreads();
    }
    #pragma unroll
    for (int i = 0; i < 4; i++) {
        int m = m0 + tx*4 + i;
        if (m < B*U) {
            int b = m / U, s = m % U;
            float* op = y + ((size_t)b*S + s)*D + n0 + ty*4;
            #pragma unroll
            for (int j = 0; j < 4; j++)
                op[j] = acc[i][j] + bo[n0 + ty*4 + j];
        }
    }
}

// ---------------- broadcast the uniform rows (s >= U) ----------------
__global__ void bcast_kernel(float* __restrict__ y) {
    int id = blockIdx.x * blockDim.x + threadIdx.x;
    const int per_b = (S - U) * (D/4);
    const int total = B * per_b;
    if (id >= total) return;
    int b = id / per_b;
    int r = id % per_b;
    int s = U + r / (D/4);
    int d4 = r % (D/4);
    float4 v = *(const float4*)(g_ybase + b*D + d4*4);
    *(float4*)(y + ((size_t)b*S + s)*D + d4*4) = v;
}

extern "C" void kernel_launch(void* const* d_in, const int* in_sizes, int n_in,
                              void* d_out, int out_size) {
    const float* x  = (const float*)d_in[0];
    const float* wq = (const float*)d_in[1];
    const float* bq = (const float*)d_in[2];
    const float* wk = (const float*)d_in[3];
    const float* bk = (const float*)d_in[4];
    const float* wv = (const float*)d_in[5];
    const float* bv = (const float*)d_in[6];
    const float* wo = (const float*)d_in[7];
    const float* bo = (const float*)d_in[8];
    float* y = (float*)d_out;

    cudaFuncSetAttribute(scores_mma_kernel, cudaFuncAttributeMaxDynamicSharedMemorySize, SM2_TOTAL);
    cudaFuncSetAttribute(proj_mma_kernel, cudaFuncAttributeMaxDynamicSharedMemorySize, PJ_SM_TOTAL);

    {
        const int total = XU + 2*WU;
        convert_xw_kernel<<<(total + 255)/256, 256>>>(x, wq, wk);          // u1
    }

    dim3 pg(B*S/128, D/64, 2);
    proj_mma_kernel<<<pg, 256, PJ_SM_TOTAL>>>(bq, bk);                     // u2

    sumx_part_kernel<<<B*32, 512>>>(x);                                    // u3

    dim3 sg(BH, 8);
    scores_mma_kernel<<<sg, 128, SM2_TOTAL>>>();                           // u4 <- ncu

    xsum_sumk_kernel<<<B, 512>>>(wk, bk);                                  // u5

    fixup_kernel<<<BH*S/8, 256>>>();                                       // u6

    topk_kernel<<<BH, 256>>>();                                            // u7

    meanv_ybase_kernel<<<B, 512>>>(wv, bv, wo, bo);                        // u8

    corr_kernel<<<BH, 256>>>(x, wv, bv);                                   // u9

    dim3 og((B*U + 63)/64, D/64);
    outproj_kernel<<<og, 256>>>(wo, bo, y);                                // u10

    const int per_b = (S - U) * (D/4);
    bcast_kernel<<<(B*per_b + 255)/256, 256>>>(y);                         // u11
}